// round 10
// baseline (speedup 1.0000x reference)
#include <cuda_runtime.h>
#include <math.h>

#define BB 64
#define CC 1024
#define QQ 256
#define DD 128
#define OUTD (4*DD)
#define NEGV (-1e30f)
#define NCHUNK 8
#define LD 36          // f32 smem leading dim

// ---- scratch (device globals: allocation-free) ----
__device__ float g_S[(size_t)BB*CC*QQ];      // final S, 64 MB
__device__ float g_s0[BB*CC];
__device__ float g_s1[BB*QQ];
__device__ float g_pm[BB*NCHUNK*QQ];
__device__ float g_ps[BB*NCHUNK*QQ];
__device__ float g_colM[BB*QQ];
__device__ float g_colZ[BB*QQ];
__device__ float g_rowM[BB*CC];
__device__ float g_rowZ[BB*CC];
__device__ float g_AT[(size_t)BB*DD*QQ];     // (S_T @ x_cont)^T [b][d][q], tf32-rounded
__device__ float g_xcT[(size_t)BB*DD*CC];    // xc^T [b][d][c]
__device__ float g_xqT[(size_t)BB*DD*QQ];    // xq^T [b][d][q]

// ---------------------------------------------------------------------------
// tf32 helpers
// ---------------------------------------------------------------------------
__device__ __forceinline__ float f2tf(float x)
{
    unsigned u;
    asm("cvt.rna.tf32.f32 %0, %1;" : "=r"(u) : "f"(x));
    return __uint_as_float(u);
}
__device__ __forceinline__ float4 f2tf4(float4 v)
{
    v.x = f2tf(v.x); v.y = f2tf(v.y); v.z = f2tf(v.z); v.w = f2tf(v.w);
    return v;
}

__device__ __forceinline__ void mma16808(float* c, const unsigned* a, const unsigned* b)
{
    asm volatile(
        "mma.sync.aligned.m16n8k8.row.col.f32.tf32.tf32.f32 "
        "{%0,%1,%2,%3},{%4,%5,%6,%7},{%8,%9},{%0,%1,%2,%3};"
        : "+f"(c[0]), "+f"(c[1]), "+f"(c[2]), "+f"(c[3])
        : "r"(a[0]), "r"(a[1]), "r"(a[2]), "r"(a[3]), "r"(b[0]), "r"(b[1]));
}

__device__ __forceinline__ void ldsm4f(unsigned* r, const float* p)
{
    unsigned addr = (unsigned)__cvta_generic_to_shared(p);
    asm volatile("ldmatrix.sync.aligned.m8n8.x4.shared.b16 {%0,%1,%2,%3},[%4];"
                 : "=r"(r[0]), "=r"(r[1]), "=r"(r[2]), "=r"(r[3]) : "r"(addr));
}

__device__ __forceinline__ void ldfragA(unsigned a[4], const float* tile,
                                        int row0, int ks, int lane)
{
    int m = lane >> 3;
    const float* p = tile + (row0 + ((m & 1) << 3) + (lane & 7))*LD
                          + ks + ((m >> 1) << 2);
    ldsm4f(a, p);
}

__device__ __forceinline__ void ldfragB2(unsigned bq[4], const float* tile,
                                         int nrow0, int ks, int lane)
{
    int m = lane >> 3;
    const float* p = tile + (nrow0 + ((m >> 1) << 3) + (lane & 7))*LD
                          + ks + ((m & 1) << 2);
    ldsm4f(bq, p);
}

// ---------------------------------------------------------------------------
// transpose: src[b][R][C] -> dst[b][C][R]
// ---------------------------------------------------------------------------
__global__ void ktrans(const float* __restrict__ src, float* __restrict__ dst,
                       int R, int C)
{
    __shared__ float t[32][33];
    int b  = blockIdx.z;
    int r0 = blockIdx.y * 32, c0 = blockIdx.x * 32;
    int x = threadIdx.x, y = threadIdx.y;
#pragma unroll
    for (int i = 0; i < 32; i += 8)
        t[y+i][x] = src[((size_t)b*R + r0+y+i)*C + c0+x];
    __syncthreads();
#pragma unroll
    for (int i = 0; i < 32; i += 8)
        dst[((size_t)b*C + c0+y+i)*R + r0+x] = t[x][y+i];
}

// ---------------------------------------------------------------------------
// projections
// ---------------------------------------------------------------------------
__device__ __forceinline__ float row_dot(const float* __restrict__ xr,
                                         const float* __restrict__ W, int lane)
{
    float s = 0.f;
#pragma unroll
    for (int d = 0; d < DD; d += 32) s += xr[d + lane] * W[d + lane];
#pragma unroll
    for (int o = 16; o > 0; o >>= 1) s += __shfl_xor_sync(0xffffffffu, s, o);
    return s;
}

__global__ void k_s0(const float* __restrict__ x, const float* __restrict__ W,
                     const float* __restrict__ bias)
{
    int warp = (blockIdx.x * blockDim.x + threadIdx.x) >> 5;
    int lane = threadIdx.x & 31;
    if (warp >= BB*CC) return;
    float s = row_dot(x + (size_t)warp * DD, W, lane);
    if (lane == 0) g_s0[warp] = s + bias[0];
}

__global__ void k_s1(const float* __restrict__ x, const float* __restrict__ W)
{
    int warp = (blockIdx.x * blockDim.x + threadIdx.x) >> 5;
    int lane = threadIdx.x & 31;
    if (warp >= BB*QQ) return;
    float s = row_dot(x + (size_t)warp * DD, W, lane);
    if (lane == 0) g_s1[warp] = s;
}

// ---------------------------------------------------------------------------
// K1: S = (xc*W2) @ xq^T + s0 + s1.  tf32, reg-prefetch pipelined.
// BLK 128c x 128q, warp 32x64.
// ---------------------------------------------------------------------------
__global__ __launch_bounds__(256) void k1_S(const float* __restrict__ xc,
                                            const float* __restrict__ xq,
                                            const float* __restrict__ W2)
{
    __shared__ __align__(16) float As[128*LD];
    __shared__ __align__(16) float Bs[128*LD];
    __shared__ float W2s[DD];

    int b  = blockIdx.z;
    int c0 = blockIdx.y * 128;
    int q0 = blockIdx.x * 128;
    int tid = threadIdx.x;
    int warp = tid >> 5, lane = tid & 31;
    int wm = (warp >> 1) * 32, wn = (warp & 1) * 64;
    if (tid < DD) W2s[tid] = W2[tid];

    // per-thread fill coordinates (constant over chunks)
    int fr = tid >> 1;                 // row 0..127 (2 thr/row)
    int fd = (tid & 1) * 16;           // 16-float half of 32-chunk... no: 4 float4 per thread
    // use original scheme: 4 slots of (r, d4)
    int r_[4], d_[4];
#pragma unroll
    for (int i = 0; i < 4; i++) {
        int f = tid + i*256;
        r_[i] = f >> 3; d_[i] = (f & 7) * 4;
    }
    (void)fr; (void)fd;

    float4 pa[4], pb[4];
    float acc[2][8][4] = {};

    // prefetch chunk 0
#pragma unroll
    for (int i = 0; i < 4; i++) {
        pa[i] = *(const float4*)&xc[((size_t)(b*CC + c0 + r_[i]))*DD + d_[i]];
        pb[i] = *(const float4*)&xq[((size_t)(b*QQ + q0 + r_[i]))*DD + d_[i]];
    }
    __syncthreads();   // W2s ready

    for (int k0 = 0; k0 < DD; k0 += 32) {
        // store current chunk (W2 scale on A)
#pragma unroll
        for (int i = 0; i < 4; i++) {
            float4 v = pa[i];
            v.x *= W2s[k0+d_[i]+0]; v.y *= W2s[k0+d_[i]+1];
            v.z *= W2s[k0+d_[i]+2]; v.w *= W2s[k0+d_[i]+3];
            *(float4*)&As[r_[i]*LD + d_[i]] = f2tf4(v);
            *(float4*)&Bs[r_[i]*LD + d_[i]] = f2tf4(pb[i]);
        }
        __syncthreads();
        // issue next-chunk loads (land during MMAs)
        if (k0 + 32 < DD) {
#pragma unroll
            for (int i = 0; i < 4; i++) {
                pa[i] = *(const float4*)&xc[((size_t)(b*CC + c0 + r_[i]))*DD + k0+32 + d_[i]];
                pb[i] = *(const float4*)&xq[((size_t)(b*QQ + q0 + r_[i]))*DD + k0+32 + d_[i]];
            }
        }
#pragma unroll
        for (int ks = 0; ks < 32; ks += 8) {
            unsigned a0[4], a1[4];
            ldfragA(a0, As, wm,      ks, lane);
            ldfragA(a1, As, wm + 16, ks, lane);
#pragma unroll
            for (int np = 0; np < 4; np++) {
                unsigned bq[4];
                ldfragB2(bq, Bs, wn + np*16, ks, lane);
                mma16808(acc[0][np*2],   a0, bq);
                mma16808(acc[0][np*2+1], a0, bq+2);
                mma16808(acc[1][np*2],   a1, bq);
                mma16808(acc[1][np*2+1], a1, bq+2);
            }
        }
        __syncthreads();
    }

    int g = lane >> 2, tg = lane & 3;
#pragma unroll
    for (int mi = 0; mi < 2; mi++) {
#pragma unroll
        for (int nj = 0; nj < 8; nj++) {
            int c_ = c0 + wm + mi*16 + g;
            int q_ = q0 + wn + nj*8 + tg*2;
            float s0a = g_s0[b*CC + c_];
            float s0b = g_s0[b*CC + c_ + 8];
            float s1a = g_s1[b*QQ + q_], s1b = g_s1[b*QQ + q_ + 1];
            float2 o0 = {acc[mi][nj][0] + s0a + s1a, acc[mi][nj][1] + s0a + s1b};
            *(float2*)&g_S[((size_t)(b*CC + c_))*QQ + q_] = o0;
            float2 o1 = {acc[mi][nj][2] + s0b + s1a, acc[mi][nj][3] + s0b + s1b};
            *(float2*)&g_S[((size_t)(b*CC + c_ + 8))*QQ + q_] = o1;
        }
    }
}

// ---------------------------------------------------------------------------
// K2a: per-(b,q) partial max/sumexp over c (MLP-4)
// ---------------------------------------------------------------------------
__global__ __launch_bounds__(256) void k2a_colstats(const float* __restrict__ cmask)
{
    int b = blockIdx.y;
    int chunk = blockIdx.x;
    int q = threadIdx.x;
    const float* Sp = g_S + (size_t)(b*CC)*QQ;
    const float* cm = cmask + b*CC;
    float m = -INFINITY, s = 0.f;
    int cbeg = chunk * (CC/NCHUNK);
#pragma unroll 2
    for (int c = cbeg; c < cbeg + CC/NCHUNK; c += 4) {
        float v0 = Sp[(size_t)(c+0)*QQ + q] + NEGV * (1.f - cm[c+0]);
        float v1 = Sp[(size_t)(c+1)*QQ + q] + NEGV * (1.f - cm[c+1]);
        float v2 = Sp[(size_t)(c+2)*QQ + q] + NEGV * (1.f - cm[c+2]);
        float v3 = Sp[(size_t)(c+3)*QQ + q] + NEGV * (1.f - cm[c+3]);
        float m4 = fmaxf(fmaxf(v0, v1), fmaxf(v2, v3));
        if (m4 > m) { s *= __expf(m - m4); m = m4; }
        s += __expf(v0 - m) + __expf(v1 - m) + __expf(v2 - m) + __expf(v3 - m);
    }
    g_pm[(b*NCHUNK + chunk)*QQ + q] = m;
    g_ps[(b*NCHUNK + chunk)*QQ + q] = s;
}

// K2b: per-(b,c) row max/sumexp over q
__global__ __launch_bounds__(256) void k2b_rowstats(const float* __restrict__ qmask)
{
    int row  = (blockIdx.x * blockDim.x + threadIdx.x) >> 5;
    int lane = threadIdx.x & 31;
    if (row >= BB*CC) return;
    int b = row / CC;
    const float* Sp = g_S + (size_t)row * QQ;
    const float* qm = qmask + b*QQ;
    float v[8];
    float m = -INFINITY;
#pragma unroll
    for (int j = 0; j < 8; j++) {
        v[j] = Sp[j*32 + lane] + NEGV * (1.f - qm[j*32 + lane]);
        m = fmaxf(m, v[j]);
    }
#pragma unroll
    for (int o = 16; o > 0; o >>= 1) m = fmaxf(m, __shfl_xor_sync(0xffffffffu, m, o));
    float s = 0.f;
#pragma unroll
    for (int j = 0; j < 8; j++) s += __expf(v[j] - m);
#pragma unroll
    for (int o = 16; o > 0; o >>= 1) s += __shfl_xor_sync(0xffffffffu, s, o);
    if (lane == 0) { g_rowM[row] = m; g_rowZ[row] = s; }
}

__global__ void k2c_combine()
{
    int idx = blockIdx.x * blockDim.x + threadIdx.x;
    if (idx >= BB*QQ) return;
    int b = idx / QQ, q = idx - b*QQ;
    float m = -INFINITY;
#pragma unroll
    for (int ch = 0; ch < NCHUNK; ch++)
        m = fmaxf(m, g_pm[(b*NCHUNK + ch)*QQ + q]);
    float s = 0.f;
#pragma unroll
    for (int ch = 0; ch < NCHUNK; ch++)
        s += g_ps[(b*NCHUNK + ch)*QQ + q] * __expf(g_pm[(b*NCHUNK + ch)*QQ + q] - m);
    g_colM[idx] = m;
    g_colZ[idx] = s;
}

// ---------------------------------------------------------------------------
// K3: AT[d][q] = sum_c xcT[d][c] * Pcol[c][q].  tf32, reg-prefetch pipelined.
// BLK 128d x 64q, warp 32x32.
// ---------------------------------------------------------------------------
__global__ __launch_bounds__(256) void k3_A(const float* __restrict__ cmask)
{
    __shared__ __align__(16) float As[128*LD];   // xcT [d 128][c 32]
    __shared__ __align__(16) float Bs[64*LD];    // P^T [q 64][c 32]
    __shared__ float cM[64], ciZ[64];

    int b  = blockIdx.z;
    int q0 = blockIdx.x * 64;
    int tid = threadIdx.x;
    int warp = tid >> 5, lane = tid & 31;
    int wm = (warp >> 1) * 32, wn = (warp & 1) * 32;
    if (tid < 64) {
        cM[tid]  = g_colM[b*QQ + q0 + tid];
        ciZ[tid] = 1.f / g_colZ[b*QQ + q0 + tid];
    }
    float acc[2][4][4] = {};

    // fill coords
    int ar_[4], ad_[4];
#pragma unroll
    for (int i = 0; i < 4; i++) {
        int f = tid + i*256;
        ar_[i] = f >> 3; ad_[i] = (f & 7) * 4;   // A: d row, c4 col
    }
    int sc_[2], sq_[2];
#pragma unroll
    for (int i = 0; i < 2; i++) {
        int f = tid + i*256;
        sc_[i] = f >> 4; sq_[i] = (f & 15) * 4;  // B: c row, q4 col
    }

    float4 pA[4];        // xcT prefetch
    float4 pS[2];        // S prefetch
    float pmsk[2];       // cmask prefetch
    float4 pP[2];        // processed P (tf32)

    // prefetch + process chunk 0
#pragma unroll
    for (int i = 0; i < 4; i++)
        pA[i] = *(const float4*)&g_xcT[((size_t)(b*DD + ar_[i]))*CC + ad_[i]];
#pragma unroll
    for (int i = 0; i < 2; i++) {
        pS[i] = *(const float4*)&g_S[((size_t)(b*CC + sc_[i]))*QQ + q0 + sq_[i]];
        pmsk[i] = cmask[b*CC + sc_[i]];
    }
    __syncthreads();   // cM/ciZ ready
#pragma unroll
    for (int i = 0; i < 2; i++) {
        float msk = NEGV * (1.f - pmsk[i]);
        int q4 = sq_[i];
        pP[i].x = f2tf(__expf(pS[i].x + msk - cM[q4+0]) * ciZ[q4+0]);
        pP[i].y = f2tf(__expf(pS[i].y + msk - cM[q4+1]) * ciZ[q4+1]);
        pP[i].z = f2tf(__expf(pS[i].z + msk - cM[q4+2]) * ciZ[q4+2]);
        pP[i].w = f2tf(__expf(pS[i].w + msk - cM[q4+3]) * ciZ[q4+3]);
    }

    for (int cc0 = 0; cc0 < CC; cc0 += 32) {
        // store processed chunk
#pragma unroll
        for (int i = 0; i < 4; i++)
            *(float4*)&As[ar_[i]*LD + ad_[i]] = f2tf4(pA[i]);
#pragma unroll
        for (int i = 0; i < 2; i++) {
            Bs[(sq_[i]+0)*LD + sc_[i]] = pP[i].x;
            Bs[(sq_[i]+1)*LD + sc_[i]] = pP[i].y;
            Bs[(sq_[i]+2)*LD + sc_[i]] = pP[i].z;
            Bs[(sq_[i]+3)*LD + sc_[i]] = pP[i].w;
        }
        __syncthreads();
        // issue next-chunk loads
        int nc = cc0 + 32;
        if (nc < CC) {
#pragma unroll
            for (int i = 0; i < 4; i++)
                pA[i] = *(const float4*)&g_xcT[((size_t)(b*DD + ar_[i]))*CC + nc + ad_[i]];
#pragma unroll
            for (int i = 0; i < 2; i++) {
                pS[i] = *(const float4*)&g_S[((size_t)(b*CC + nc + sc_[i]))*QQ + q0 + sq_[i]];
                pmsk[i] = cmask[b*CC + nc + sc_[i]];
            }
        }
        // MMAs (loads land underneath)
#pragma unroll
        for (int ks = 0; ks < 32; ks += 8) {
            unsigned a0[4], a1[4];
            ldfragA(a0, As, wm,      ks, lane);
            ldfragA(a1, As, wm + 16, ks, lane);
#pragma unroll
            for (int np = 0; np < 2; np++) {
                unsigned bq[4];
                ldfragB2(bq, Bs, wn + np*16, ks, lane);
                mma16808(acc[0][np*2],   a0, bq);
                mma16808(acc[0][np*2+1], a0, bq+2);
                mma16808(acc[1][np*2],   a1, bq);
                mma16808(acc[1][np*2+1], a1, bq+2);
            }
        }
        // process next chunk (after loads landed)
        if (nc < CC) {
#pragma unroll
            for (int i = 0; i < 2; i++) {
                float msk = NEGV * (1.f - pmsk[i]);
                int q4 = sq_[i];
                pP[i].x = f2tf(__expf(pS[i].x + msk - cM[q4+0]) * ciZ[q4+0]);
                pP[i].y = f2tf(__expf(pS[i].y + msk - cM[q4+1]) * ciZ[q4+1]);
                pP[i].z = f2tf(__expf(pS[i].z + msk - cM[q4+2]) * ciZ[q4+2]);
                pP[i].w = f2tf(__expf(pS[i].w + msk - cM[q4+3]) * ciZ[q4+3]);
            }
        }
        __syncthreads();
    }

    int g = lane >> 2, tg = lane & 3;
#pragma unroll
    for (int mi = 0; mi < 2; mi++) {
#pragma unroll
        for (int nj = 0; nj < 4; nj++) {
            int d_ = wm + mi*16 + g;
            int q_ = q0 + wn + nj*8 + tg*2;
            float2 o0 = {f2tf(acc[mi][nj][0]), f2tf(acc[mi][nj][1])};
            *(float2*)&g_AT[((size_t)(b*DD + d_))*QQ + q_] = o0;
            float2 o1 = {f2tf(acc[mi][nj][2]), f2tf(acc[mi][nj][3])};
            *(float2*)&g_AT[((size_t)(b*DD + d_ + 8))*QQ + q_] = o1;
        }
    }
}

// ---------------------------------------------------------------------------
// K4: c2q = Prow @ xq ; q2c = Prow @ A ; concat.  tf32, reg-prefetch pipelined.
// BLK 64c x 128d, warp 16x64.
// ---------------------------------------------------------------------------
__global__ __launch_bounds__(256) void k4_out(const float* __restrict__ xc,
                                              const float* __restrict__ qmask,
                                              float* __restrict__ out)
{
    __shared__ __align__(16) float As[64*LD];
    __shared__ __align__(16) float B1s[128*LD];
    __shared__ __align__(16) float B2s[128*LD];
    __shared__ float rM[64], riZ[64], qmn[QQ];

    int b  = blockIdx.z;
    int c0 = blockIdx.x * 64;
    int tid = threadIdx.x;
    int warp = tid >> 5, lane = tid & 31;
    int wm = (warp >> 1) * 16, wn = (warp & 1) * 64;
    if (tid < 64) {
        rM[tid]  = g_rowM[b*CC + c0 + tid];
        riZ[tid] = 1.f / g_rowZ[b*CC + c0 + tid];
    }
    qmn[tid] = NEGV * (1.f - qmask[b*QQ + tid]);

    float acc1[8][4] = {};
    float acc2[8][4] = {};

    int sc_[2], sq_[2];
#pragma unroll
    for (int i = 0; i < 2; i++) {
        int f = tid + i*256;
        sc_[i] = f >> 3; sq_[i] = (f & 7) * 4;   // A: c row, q4
    }
    int bd_[4], bq_[4];
#pragma unroll
    for (int i = 0; i < 4; i++) {
        int f = tid + i*256;
        bd_[i] = f >> 3; bq_[i] = (f & 7) * 4;   // B: d row, q4
    }

    float4 pS[2], pP[2];
    float4 pB1[4], pB2[4];

    // prefetch chunk 0
#pragma unroll
    for (int i = 0; i < 2; i++)
        pS[i] = *(const float4*)&g_S[((size_t)(b*CC + c0 + sc_[i]))*QQ + sq_[i]];
#pragma unroll
    for (int i = 0; i < 4; i++) {
        size_t gb = ((size_t)(b*DD + bd_[i]))*QQ + bq_[i];
        pB1[i] = *(const float4*)&g_xqT[gb];
        pB2[i] = *(const float4*)&g_AT[gb];
    }
    __syncthreads();   // rM/riZ/qmn ready
#pragma unroll
    for (int i = 0; i < 2; i++) {
        float m = rM[sc_[i]], iz = riZ[sc_[i]];
        int q4 = sq_[i];
        pP[i].x = f2tf(__expf(pS[i].x + qmn[q4+0] - m) * iz);
        pP[i].y = f2tf(__expf(pS[i].y + qmn[q4+1] - m) * iz);
        pP[i].z = f2tf(__expf(pS[i].z + qmn[q4+2] - m) * iz);
        pP[i].w = f2tf(__expf(pS[i].w + qmn[q4+3] - m) * iz);
    }

    for (int qq0 = 0; qq0 < QQ; qq0 += 32) {
        // store
#pragma unroll
        for (int i = 0; i < 2; i++)
            *(float4*)&As[sc_[i]*LD + sq_[i]] = pP[i];
#pragma unroll
        for (int i = 0; i < 4; i++) {
            *(float4*)&B1s[bd_[i]*LD + bq_[i]] = f2tf4(pB1[i]);
            *(float4*)&B2s[bd_[i]*LD + bq_[i]] = pB2[i];   // pre-rounded
        }
        __syncthreads();
        int nq = qq0 + 32;
        if (nq < QQ) {
#pragma unroll
            for (int i = 0; i < 2; i++)
                pS[i] = *(const float4*)&g_S[((size_t)(b*CC + c0 + sc_[i]))*QQ + nq + sq_[i]];
#pragma unroll
            for (int i = 0; i < 4; i++) {
                size_t gb = ((size_t)(b*DD + bd_[i]))*QQ + nq + bq_[i];
                pB1[i] = *(const float4*)&g_xqT[gb];
                pB2[i] = *(const float4*)&g_AT[gb];
            }
        }
#pragma unroll
        for (int ks = 0; ks < 32; ks += 8) {
            unsigned a[4];
            ldfragA(a, As, wm, ks, lane);
#pragma unroll
            for (int np = 0; np < 4; np++) {
                unsigned bq[4];
                ldfragB2(bq, B1s, wn + np*16, ks, lane);
                mma16808(acc1[np*2],   a, bq);
                mma16808(acc1[np*2+1], a, bq+2);
                ldfragB2(bq, B2s, wn + np*16, ks, lane);
                mma16808(acc2[np*2],   a, bq);
                mma16808(acc2[np*2+1], a, bq+2);
            }
        }
        if (nq < QQ) {
#pragma unroll
            for (int i = 0; i < 2; i++) {
                float m = rM[sc_[i]], iz = riZ[sc_[i]];
                int q4 = sq_[i];
                pP[i].x = f2tf(__expf(pS[i].x + qmn[nq+q4+0] - m) * iz);
                pP[i].y = f2tf(__expf(pS[i].y + qmn[nq+q4+1] - m) * iz);
                pP[i].z = f2tf(__expf(pS[i].z + qmn[nq+q4+2] - m) * iz);
                pP[i].w = f2tf(__expf(pS[i].w + qmn[nq+q4+3] - m) * iz);
            }
        }
        __syncthreads();
    }

    int g = lane >> 2, tg = lane & 3;
#pragma unroll
    for (int nj = 0; nj < 8; nj++) {
        int d_ = wn + nj*8 + tg*2;
#pragma unroll
        for (int half = 0; half < 2; half++) {
            int c_ = c0 + wm + g + half*8;
            size_t rbase = (size_t)(b*CC + c_);
            float2 xv = *(const float2*)&xc[rbase*DD + d_];
            float2 c2q = {half ? acc1[nj][2] : acc1[nj][0],
                          half ? acc1[nj][3] : acc1[nj][1]};
            float2 q2c = {half ? acc2[nj][2] : acc2[nj][0],
                          half ? acc2[nj][3] : acc2[nj][1]};
            float* ob = out + rbase*OUTD;
            *(float2*)&ob[d_] = xv;
            *(float2*)&ob[DD + d_] = c2q;
            float2 m1 = {xv.x*c2q.x, xv.y*c2q.y};
            *(float2*)&ob[2*DD + d_] = m1;
            float2 m2 = {xv.x*q2c.x, xv.y*q2c.y};
            *(float2*)&ob[3*DD + d_] = m2;
        }
    }
}

// ---------------------------------------------------------------------------
extern "C" void kernel_launch(void* const* d_in, const int* in_sizes, int n_in,
                              void* d_out, int out_size)
{
    const float* xc   = (const float*)d_in[0];
    const float* xq   = (const float*)d_in[1];
    const float* cm   = (const float*)d_in[2];
    const float* qm   = (const float*)d_in[3];
    const float* W0   = (const float*)d_in[4];
    const float* W1   = (const float*)d_in[5];
    const float* W2   = (const float*)d_in[6];
    const float* bias = (const float*)d_in[7];
    float* out = (float*)d_out;

    k_s0<<<BB*CC/8, 256>>>(xc, W0, bias);
    k_s1<<<BB*QQ/8, 256>>>(xq, W1);
    {
        float* xcT; cudaGetSymbolAddress((void**)&xcT, g_xcT);
        float* xqT; cudaGetSymbolAddress((void**)&xqT, g_xqT);
        ktrans<<<dim3(DD/32, CC/32, BB), dim3(32,8)>>>(xc, xcT, CC, DD);
        ktrans<<<dim3(DD/32, QQ/32, BB), dim3(32,8)>>>(xq, xqT, QQ, DD);
    }
    k1_S<<<dim3(QQ/128, CC/128, BB), 256>>>(xc, xq, W2);
    k2a_colstats<<<dim3(NCHUNK, BB), 256>>>(cm);
    k2b_rowstats<<<BB*CC/8, 256>>>(qm);
    k2c_combine<<<BB*QQ/256, 256>>>();
    k3_A<<<dim3(QQ/64, 1, BB), 256>>>(cm);
    k4_out<<<dim3(CC/64, 1, BB), 256>>>(xc, qm, out);
}

// round 11
// speedup vs baseline: 1.3338x; 1.3338x over previous
#include <cuda_runtime.h>
#include <math.h>

#define BB 64
#define CC 1024
#define QQ 256
#define DD 128
#define OUTD (4*DD)
#define NEGV (-1e30f)
#define NCHUNK 8
#define LD 36          // f32 smem leading dim

// ---- scratch (device globals: allocation-free) ----
__device__ float g_S[(size_t)BB*CC*QQ];      // final S, 64 MB
__device__ float g_s0[BB*CC];
__device__ float g_s1[BB*QQ];
__device__ float g_pm[BB*NCHUNK*QQ];         // col partial max (8 c-chunks)
__device__ float g_ps[BB*NCHUNK*QQ];         // col partial sum
__device__ float g_prm[(size_t)BB*2*CC];     // row partial max (2 q-chunks)
__device__ float g_prs[(size_t)BB*2*CC];     // row partial sum
__device__ float g_colM[BB*QQ];
__device__ float g_colZ[BB*QQ];
__device__ float g_rowM[BB*CC];
__device__ float g_rowZ[BB*CC];
__device__ float g_AT[(size_t)BB*DD*QQ];     // (S_T @ x_cont)^T [b][d][q], tf32-rounded
__device__ float g_xcT[(size_t)BB*DD*CC];    // xc^T [b][d][c]
__device__ float g_xqT[(size_t)BB*DD*QQ];    // xq^T [b][d][q]

// ---------------------------------------------------------------------------
// tf32 helpers
// ---------------------------------------------------------------------------
__device__ __forceinline__ float f2tf(float x)
{
    unsigned u;
    asm("cvt.rna.tf32.f32 %0, %1;" : "=r"(u) : "f"(x));
    return __uint_as_float(u);
}
__device__ __forceinline__ float4 f2tf4(float4 v)
{
    v.x = f2tf(v.x); v.y = f2tf(v.y); v.z = f2tf(v.z); v.w = f2tf(v.w);
    return v;
}

__device__ __forceinline__ void mma16808(float* c, const unsigned* a, const unsigned* b)
{
    asm volatile(
        "mma.sync.aligned.m16n8k8.row.col.f32.tf32.tf32.f32 "
        "{%0,%1,%2,%3},{%4,%5,%6,%7},{%8,%9},{%0,%1,%2,%3};"
        : "+f"(c[0]), "+f"(c[1]), "+f"(c[2]), "+f"(c[3])
        : "r"(a[0]), "r"(a[1]), "r"(a[2]), "r"(a[3]), "r"(b[0]), "r"(b[1]));
}

__device__ __forceinline__ void ldsm4f(unsigned* r, const float* p)
{
    unsigned addr = (unsigned)__cvta_generic_to_shared(p);
    asm volatile("ldmatrix.sync.aligned.m8n8.x4.shared.b16 {%0,%1,%2,%3},[%4];"
                 : "=r"(r[0]), "=r"(r[1]), "=r"(r[2]), "=r"(r[3]) : "r"(addr));
}

__device__ __forceinline__ void ldfragA(unsigned a[4], const float* tile,
                                        int row0, int ks, int lane)
{
    int m = lane >> 3;
    const float* p = tile + (row0 + ((m & 1) << 3) + (lane & 7))*LD
                          + ks + ((m >> 1) << 2);
    ldsm4f(a, p);
}

__device__ __forceinline__ void ldfragB2(unsigned bq[4], const float* tile,
                                         int nrow0, int ks, int lane)
{
    int m = lane >> 3;
    const float* p = tile + (nrow0 + ((m >> 1) << 3) + (lane & 7))*LD
                          + ks + ((m & 1) << 2);
    ldsm4f(bq, p);
}

// ---------------------------------------------------------------------------
// transpose: src[b][R][C] -> dst[b][C][R]
// ---------------------------------------------------------------------------
__global__ void ktrans(const float* __restrict__ src, float* __restrict__ dst,
                       int R, int C)
{
    __shared__ float t[32][33];
    int b  = blockIdx.z;
    int r0 = blockIdx.y * 32, c0 = blockIdx.x * 32;
    int x = threadIdx.x, y = threadIdx.y;
#pragma unroll
    for (int i = 0; i < 32; i += 8)
        t[y+i][x] = src[((size_t)b*R + r0+y+i)*C + c0+x];
    __syncthreads();
#pragma unroll
    for (int i = 0; i < 32; i += 8)
        dst[((size_t)b*C + c0+y+i)*R + r0+x] = t[x][y+i];
}

// ---------------------------------------------------------------------------
// projections
// ---------------------------------------------------------------------------
__device__ __forceinline__ float row_dot(const float* __restrict__ xr,
                                         const float* __restrict__ W, int lane)
{
    float s = 0.f;
#pragma unroll
    for (int d = 0; d < DD; d += 32) s += xr[d + lane] * W[d + lane];
#pragma unroll
    for (int o = 16; o > 0; o >>= 1) s += __shfl_xor_sync(0xffffffffu, s, o);
    return s;
}

__global__ void k_s0(const float* __restrict__ x, const float* __restrict__ W,
                     const float* __restrict__ bias)
{
    int warp = (blockIdx.x * blockDim.x + threadIdx.x) >> 5;
    int lane = threadIdx.x & 31;
    if (warp >= BB*CC) return;
    float s = row_dot(x + (size_t)warp * DD, W, lane);
    if (lane == 0) g_s0[warp] = s + bias[0];
}

__global__ void k_s1(const float* __restrict__ x, const float* __restrict__ W)
{
    int warp = (blockIdx.x * blockDim.x + threadIdx.x) >> 5;
    int lane = threadIdx.x & 31;
    if (warp >= BB*QQ) return;
    float s = row_dot(x + (size_t)warp * DD, W, lane);
    if (lane == 0) g_s1[warp] = s;
}

// ---------------------------------------------------------------------------
// K1: S = (xc*W2) @ xq^T + s0 + s1  (R8 mainloop, unchanged), PLUS epilogue
// stats: partial row max/sum over the block's 128-q window, partial col
// max/sum over the block's 128-c window.
// BLK 128c x 128q, warp 32x64. grid (2 qblk, 8 cblk, B).
// ---------------------------------------------------------------------------
__global__ __launch_bounds__(256) void k1_S(const float* __restrict__ xc,
                                            const float* __restrict__ xq,
                                            const float* __restrict__ W2,
                                            const float* __restrict__ cmask,
                                            const float* __restrict__ qmask)
{
    __shared__ __align__(16) float As[128*LD];
    __shared__ __align__(16) float Bs[128*LD];
    __shared__ float W2s[DD];
    __shared__ float qmn_s[128], cmn_s[128];
    __shared__ float rmaxS[128][2], rsumS[128][2];
    __shared__ float cstat[128][4], cmaxf[128];

    int b  = blockIdx.z;
    int qblk = blockIdx.x, cblk = blockIdx.y;
    int c0 = cblk * 128;
    int q0 = qblk * 128;
    int tid = threadIdx.x;
    int warp = tid >> 5, lane = tid & 31;
    int warp_m = warp >> 1, warp_n = warp & 1;
    int wm = warp_m * 32, wn = warp_n * 64;
    if (tid < DD) W2s[tid] = W2[tid];
    if (tid < 128) {
        qmn_s[tid] = NEGV * (1.f - qmask[b*QQ + q0 + tid]);
        cmn_s[tid] = NEGV * (1.f - cmask[b*CC + c0 + tid]);
    }

    float acc[2][8][4] = {};
    __syncthreads();

    for (int k0 = 0; k0 < DD; k0 += 32) {
#pragma unroll
        for (int i = 0; i < 4; i++) {
            int f = tid + i*256;
            int r = f >> 3, d4 = (f & 7) * 4;
            float4 v = *(const float4*)&xc[((size_t)(b*CC + c0 + r))*DD + k0 + d4];
            v.x *= W2s[k0+d4+0]; v.y *= W2s[k0+d4+1];
            v.z *= W2s[k0+d4+2]; v.w *= W2s[k0+d4+3];
            *(float4*)&As[r*LD + d4] = f2tf4(v);
            float4 u = *(const float4*)&xq[((size_t)(b*QQ + q0 + r))*DD + k0 + d4];
            *(float4*)&Bs[r*LD + d4] = f2tf4(u);
        }
        __syncthreads();
#pragma unroll
        for (int ks = 0; ks < 32; ks += 8) {
            unsigned a0[4], a1[4];
            ldfragA(a0, As, wm,      ks, lane);
            ldfragA(a1, As, wm + 16, ks, lane);
#pragma unroll
            for (int np = 0; np < 4; np++) {
                unsigned bq[4];
                ldfragB2(bq, Bs, wn + np*16, ks, lane);
                mma16808(acc[0][np*2],   a0, bq);
                mma16808(acc[0][np*2+1], a0, bq+2);
                mma16808(acc[1][np*2],   a1, bq);
                mma16808(acc[1][np*2+1], a1, bq+2);
            }
        }
        __syncthreads();
    }

    int g = lane >> 2, tg = lane & 3;

    // ---- finalize S (add s0+s1) in-register, store ----
#pragma unroll
    for (int mi = 0; mi < 2; mi++) {
#pragma unroll
        for (int nj = 0; nj < 8; nj++) {
            int c_ = c0 + wm + mi*16 + g;
            int q_ = q0 + wn + nj*8 + tg*2;
            float s0a = g_s0[b*CC + c_];
            float s0b = g_s0[b*CC + c_ + 8];
            float s1a = g_s1[b*QQ + q_], s1b = g_s1[b*QQ + q_ + 1];
            acc[mi][nj][0] += s0a + s1a; acc[mi][nj][1] += s0a + s1b;
            acc[mi][nj][2] += s0b + s1a; acc[mi][nj][3] += s0b + s1b;
            float2 o0 = {acc[mi][nj][0], acc[mi][nj][1]};
            *(float2*)&g_S[((size_t)(b*CC + c_))*QQ + q_] = o0;
            float2 o1 = {acc[mi][nj][2], acc[mi][nj][3]};
            *(float2*)&g_S[((size_t)(b*CC + c_ + 8))*QQ + q_] = o1;
        }
    }

    // ---- row stats: partial over this block's 128-q window ----
    // thread holds rows (mi, half): local row = wm + mi*16 + g + half*8
    {
        float rmv[2][2] = {{-INFINITY,-INFINITY},{-INFINITY,-INFINITY}};
#pragma unroll
        for (int mi = 0; mi < 2; mi++)
#pragma unroll
            for (int nj = 0; nj < 8; nj++) {
                int ql = wn + nj*8 + tg*2;
                float ma = qmn_s[ql], mb = qmn_s[ql+1];
                rmv[mi][0] = fmaxf(rmv[mi][0], fmaxf(acc[mi][nj][0]+ma, acc[mi][nj][1]+mb));
                rmv[mi][1] = fmaxf(rmv[mi][1], fmaxf(acc[mi][nj][2]+ma, acc[mi][nj][3]+mb));
            }
#pragma unroll
        for (int o = 1; o <= 2; o <<= 1) {
            rmv[0][0] = fmaxf(rmv[0][0], __shfl_xor_sync(0xffffffffu, rmv[0][0], o));
            rmv[0][1] = fmaxf(rmv[0][1], __shfl_xor_sync(0xffffffffu, rmv[0][1], o));
            rmv[1][0] = fmaxf(rmv[1][0], __shfl_xor_sync(0xffffffffu, rmv[1][0], o));
            rmv[1][1] = fmaxf(rmv[1][1], __shfl_xor_sync(0xffffffffu, rmv[1][1], o));
        }
        if (tg == 0) {
#pragma unroll
            for (int mi = 0; mi < 2; mi++) {
                rmaxS[wm + mi*16 + g][warp_n]     = rmv[mi][0];
                rmaxS[wm + mi*16 + g + 8][warp_n] = rmv[mi][1];
            }
        }
        __syncthreads();
        float M00 = fmaxf(rmaxS[wm + g][0],      rmaxS[wm + g][1]);
        float M01 = fmaxf(rmaxS[wm + g + 8][0],  rmaxS[wm + g + 8][1]);
        float M10 = fmaxf(rmaxS[wm + 16 + g][0], rmaxS[wm + 16 + g][1]);
        float M11 = fmaxf(rmaxS[wm + 24 + g][0], rmaxS[wm + 24 + g][1]);
        float rs[2][2] = {};
#pragma unroll
        for (int mi = 0; mi < 2; mi++) {
            float Ma = mi ? M10 : M00, Mb = mi ? M11 : M01;
#pragma unroll
            for (int nj = 0; nj < 8; nj++) {
                int ql = wn + nj*8 + tg*2;
                float ma = qmn_s[ql], mb = qmn_s[ql+1];
                rs[mi][0] += __expf(acc[mi][nj][0]+ma - Ma) + __expf(acc[mi][nj][1]+mb - Ma);
                rs[mi][1] += __expf(acc[mi][nj][2]+ma - Mb) + __expf(acc[mi][nj][3]+mb - Mb);
            }
        }
#pragma unroll
        for (int o = 1; o <= 2; o <<= 1) {
            rs[0][0] += __shfl_xor_sync(0xffffffffu, rs[0][0], o);
            rs[0][1] += __shfl_xor_sync(0xffffffffu, rs[0][1], o);
            rs[1][0] += __shfl_xor_sync(0xffffffffu, rs[1][0], o);
            rs[1][1] += __shfl_xor_sync(0xffffffffu, rs[1][1], o);
        }
        if (tg == 0) {
#pragma unroll
            for (int mi = 0; mi < 2; mi++) {
                rsumS[wm + mi*16 + g][warp_n]     = rs[mi][0];
                rsumS[wm + mi*16 + g + 8][warp_n] = rs[mi][1];
            }
        }
        __syncthreads();
        if (tid < 128) {
            float m = fmaxf(rmaxS[tid][0], rmaxS[tid][1]);
            float s = rsumS[tid][0] + rsumS[tid][1];   // both used combined max
            size_t idx = ((size_t)b*2 + qblk)*CC + c0 + tid;
            g_prm[idx] = m;
            g_prs[idx] = s;
        }
    }

    // ---- col stats: partial over this block's 128-c window ----
    {
        float mk0 = cmn_s[wm + g],      mk1 = cmn_s[wm + g + 8];
        float mk2 = cmn_s[wm + 16 + g], mk3 = cmn_s[wm + 24 + g];
        float cmv[8][2];
#pragma unroll
        for (int nj = 0; nj < 8; nj++) {
            cmv[nj][0] = fmaxf(fmaxf(acc[0][nj][0]+mk0, acc[0][nj][2]+mk1),
                               fmaxf(acc[1][nj][0]+mk2, acc[1][nj][2]+mk3));
            cmv[nj][1] = fmaxf(fmaxf(acc[0][nj][1]+mk0, acc[0][nj][3]+mk1),
                               fmaxf(acc[1][nj][1]+mk2, acc[1][nj][3]+mk3));
        }
#pragma unroll
        for (int o = 4; o <= 16; o <<= 1)
#pragma unroll
            for (int nj = 0; nj < 8; nj++) {
                cmv[nj][0] = fmaxf(cmv[nj][0], __shfl_xor_sync(0xffffffffu, cmv[nj][0], o));
                cmv[nj][1] = fmaxf(cmv[nj][1], __shfl_xor_sync(0xffffffffu, cmv[nj][1], o));
            }
        if (lane < 4) {
#pragma unroll
            for (int nj = 0; nj < 8; nj++) {
                int ql = wn + nj*8 + tg*2;
                cstat[ql][warp_m]   = cmv[nj][0];
                cstat[ql+1][warp_m] = cmv[nj][1];
            }
        }
        __syncthreads();
        if (tid < 128)
            cmaxf[tid] = fmaxf(fmaxf(cstat[tid][0], cstat[tid][1]),
                               fmaxf(cstat[tid][2], cstat[tid][3]));
        __syncthreads();
        float cs[8][2];
#pragma unroll
        for (int nj = 0; nj < 8; nj++) {
            int ql = wn + nj*8 + tg*2;
            float Mc0 = cmaxf[ql], Mc1 = cmaxf[ql+1];
            cs[nj][0] = __expf(acc[0][nj][0]+mk0 - Mc0) + __expf(acc[0][nj][2]+mk1 - Mc0)
                      + __expf(acc[1][nj][0]+mk2 - Mc0) + __expf(acc[1][nj][2]+mk3 - Mc0);
            cs[nj][1] = __expf(acc[0][nj][1]+mk0 - Mc1) + __expf(acc[0][nj][3]+mk1 - Mc1)
                      + __expf(acc[1][nj][1]+mk2 - Mc1) + __expf(acc[1][nj][3]+mk3 - Mc1);
        }
#pragma unroll
        for (int o = 4; o <= 16; o <<= 1)
#pragma unroll
            for (int nj = 0; nj < 8; nj++) {
                cs[nj][0] += __shfl_xor_sync(0xffffffffu, cs[nj][0], o);
                cs[nj][1] += __shfl_xor_sync(0xffffffffu, cs[nj][1], o);
            }
        __syncthreads();   // cstat reads done; reuse for sums
        if (lane < 4) {
#pragma unroll
            for (int nj = 0; nj < 8; nj++) {
                int ql = wn + nj*8 + tg*2;
                cstat[ql][warp_m]   = cs[nj][0];
                cstat[ql+1][warp_m] = cs[nj][1];
            }
        }
        __syncthreads();
        if (tid < 128) {
            float s = cstat[tid][0] + cstat[tid][1] + cstat[tid][2] + cstat[tid][3];
            int idx = (b*NCHUNK + cblk)*QQ + q0 + tid;
            g_pm[idx] = cmaxf[tid];
            g_ps[idx] = s;
        }
    }
}

// ---------------------------------------------------------------------------
// K2c: combine the NCHUNK col partials ; K2r: combine the 2 row partials
// ---------------------------------------------------------------------------
__global__ void k2c_combine()
{
    int idx = blockIdx.x * blockDim.x + threadIdx.x;
    if (idx >= BB*QQ) return;
    int b = idx / QQ, q = idx - b*QQ;
    float m = -INFINITY;
#pragma unroll
    for (int ch = 0; ch < NCHUNK; ch++)
        m = fmaxf(m, g_pm[(b*NCHUNK + ch)*QQ + q]);
    float s = 0.f;
#pragma unroll
    for (int ch = 0; ch < NCHUNK; ch++)
        s += g_ps[(b*NCHUNK + ch)*QQ + q] * __expf(g_pm[(b*NCHUNK + ch)*QQ + q] - m);
    g_colM[idx] = m;
    g_colZ[idx] = s;
}

__global__ void k2r_combine()
{
    int idx = blockIdx.x * blockDim.x + threadIdx.x;
    if (idx >= BB*CC) return;
    int b = idx / CC, c = idx - b*CC;
    float m0 = g_prm[((size_t)b*2 + 0)*CC + c];
    float m1 = g_prm[((size_t)b*2 + 1)*CC + c];
    float s0 = g_prs[((size_t)b*2 + 0)*CC + c];
    float s1 = g_prs[((size_t)b*2 + 1)*CC + c];
    float m = fmaxf(m0, m1);
    g_rowM[idx] = m;
    g_rowZ[idx] = s0 * __expf(m0 - m) + s1 * __expf(m1 - m);
}

// ---------------------------------------------------------------------------
// K3: AT[d][q] = sum_c xcT[d][c] * Pcol[c][q].  tf32. (R8 version)
// BLK 128d x 64q, warp 32x32.
// ---------------------------------------------------------------------------
__global__ __launch_bounds__(256) void k3_A(const float* __restrict__ cmask)
{
    __shared__ __align__(16) float As[128*LD];   // xcT [d 128][c 32]
    __shared__ __align__(16) float Bs[64*LD];    // P^T [q 64][c 32]
    __shared__ float cM[64], ciZ[64], cmn[32];

    int b  = blockIdx.z;
    int q0 = blockIdx.x * 64;
    int tid = threadIdx.x;
    int warp = tid >> 5, lane = tid & 31;
    int wm = (warp >> 1) * 32, wn = (warp & 1) * 32;
    if (tid < 64) {
        cM[tid]  = g_colM[b*QQ + q0 + tid];
        ciZ[tid] = 1.f / g_colZ[b*QQ + q0 + tid];
    }
    float acc[2][4][4] = {};

    for (int cc0 = 0; cc0 < CC; cc0 += 32) {
        if (tid < 32) cmn[tid] = NEGV * (1.f - cmask[b*CC + cc0 + tid]);
        __syncthreads();
#pragma unroll
        for (int i = 0; i < 4; i++) {
            int f = tid + i*256;
            int d = f >> 3, c4 = (f & 7) * 4;
            float4 v = *(const float4*)&g_xcT[((size_t)(b*DD + d))*CC + cc0 + c4];
            *(float4*)&As[d*LD + c4] = f2tf4(v);
        }
#pragma unroll
        for (int i = 0; i < 2; i++) {
            int f = tid + i*256;
            int c = f >> 4, q4 = (f & 15) * 4;
            float4 s4 = *(const float4*)&g_S[((size_t)(b*CC + cc0 + c))*QQ + q0 + q4];
            float msk = cmn[c];
            Bs[(q4+0)*LD + c] = f2tf(__expf(s4.x + msk - cM[q4+0]) * ciZ[q4+0]);
            Bs[(q4+1)*LD + c] = f2tf(__expf(s4.y + msk - cM[q4+1]) * ciZ[q4+1]);
            Bs[(q4+2)*LD + c] = f2tf(__expf(s4.z + msk - cM[q4+2]) * ciZ[q4+2]);
            Bs[(q4+3)*LD + c] = f2tf(__expf(s4.w + msk - cM[q4+3]) * ciZ[q4+3]);
        }
        __syncthreads();
#pragma unroll
        for (int ks = 0; ks < 32; ks += 8) {
            unsigned a0[4], a1[4];
            ldfragA(a0, As, wm,      ks, lane);
            ldfragA(a1, As, wm + 16, ks, lane);
#pragma unroll
            for (int np = 0; np < 2; np++) {
                unsigned bq[4];
                ldfragB2(bq, Bs, wn + np*16, ks, lane);
                mma16808(acc[0][np*2],   a0, bq);
                mma16808(acc[0][np*2+1], a0, bq+2);
                mma16808(acc[1][np*2],   a1, bq);
                mma16808(acc[1][np*2+1], a1, bq+2);
            }
        }
        __syncthreads();
    }

    int g = lane >> 2, tg = lane & 3;
#pragma unroll
    for (int mi = 0; mi < 2; mi++) {
#pragma unroll
        for (int nj = 0; nj < 4; nj++) {
            int d_ = wm + mi*16 + g;
            int q_ = q0 + wn + nj*8 + tg*2;
            float2 o0 = {f2tf(acc[mi][nj][0]), f2tf(acc[mi][nj][1])};
            *(float2*)&g_AT[((size_t)(b*DD + d_))*QQ + q_] = o0;
            float2 o1 = {f2tf(acc[mi][nj][2]), f2tf(acc[mi][nj][3])};
            *(float2*)&g_AT[((size_t)(b*DD + d_ + 8))*QQ + q_] = o1;
        }
    }
}

// ---------------------------------------------------------------------------
// K4: c2q = Prow @ xq ; q2c = Prow @ A ; write concat.  tf32. (R8 version)
// BLK 64c x 128d, warp 16x64.
// ---------------------------------------------------------------------------
__global__ __launch_bounds__(256) void k4_out(const float* __restrict__ xc,
                                              const float* __restrict__ qmask,
                                              float* __restrict__ out)
{
    __shared__ __align__(16) float As[64*LD];
    __shared__ __align__(16) float B1s[128*LD];
    __shared__ __align__(16) float B2s[128*LD];
    __shared__ float rM[64], riZ[64], qmn[QQ];

    int b  = blockIdx.z;
    int c0 = blockIdx.x * 64;
    int tid = threadIdx.x;
    int warp = tid >> 5, lane = tid & 31;
    int wm = (warp >> 1) * 16, wn = (warp & 1) * 64;
    if (tid < 64) {
        rM[tid]  = g_rowM[b*CC + c0 + tid];
        riZ[tid] = 1.f / g_rowZ[b*CC + c0 + tid];
    }
    qmn[tid] = NEGV * (1.f - qmask[b*QQ + tid]);
    __syncthreads();

    float acc1[8][4] = {};
    float acc2[8][4] = {};

    for (int qq0 = 0; qq0 < QQ; qq0 += 32) {
#pragma unroll
        for (int i = 0; i < 2; i++) {
            int f = tid + i*256;
            int c = f >> 3, q4 = (f & 7) * 4;
            float4 s4 = *(const float4*)&g_S[((size_t)(b*CC + c0 + c))*QQ + qq0 + q4];
            float m = rM[c], iz = riZ[c];
            float4 p;
            p.x = f2tf(__expf(s4.x + qmn[qq0+q4+0] - m) * iz);
            p.y = f2tf(__expf(s4.y + qmn[qq0+q4+1] - m) * iz);
            p.z = f2tf(__expf(s4.z + qmn[qq0+q4+2] - m) * iz);
            p.w = f2tf(__expf(s4.w + qmn[qq0+q4+3] - m) * iz);
            *(float4*)&As[c*LD + q4] = p;
        }
#pragma unroll
        for (int i = 0; i < 4; i++) {
            int f = tid + i*256;
            int d = f >> 3, q4 = (f & 7) * 4;
            size_t gb = ((size_t)(b*DD + d))*QQ + qq0 + q4;
            float4 v = *(const float4*)&g_xqT[gb];
            *(float4*)&B1s[d*LD + q4] = f2tf4(v);
            *(float4*)&B2s[d*LD + q4] = *(const float4*)&g_AT[gb];  // pre-rounded
        }
        __syncthreads();
#pragma unroll
        for (int ks = 0; ks < 32; ks += 8) {
            unsigned a[4];
            ldfragA(a, As, wm, ks, lane);
#pragma unroll
            for (int np = 0; np < 4; np++) {
                unsigned bq[4];
                ldfragB2(bq, B1s, wn + np*16, ks, lane);
                mma16808(acc1[np*2],   a, bq);
                mma16808(acc1[np*2+1], a, bq+2);
                ldfragB2(bq, B2s, wn + np*16, ks, lane);
                mma16808(acc2[np*2],   a, bq);
                mma16808(acc2[np*2+1], a, bq+2);
            }
        }
        __syncthreads();
    }

    int g = lane >> 2, tg = lane & 3;
#pragma unroll
    for (int nj = 0; nj < 8; nj++) {
        int d_ = wn + nj*8 + tg*2;
#pragma unroll
        for (int half = 0; half < 2; half++) {
            int c_ = c0 + wm + g + half*8;
            size_t rbase = (size_t)(b*CC + c_);
            float2 xv = *(const float2*)&xc[rbase*DD + d_];
            float2 c2q = {half ? acc1[nj][2] : acc1[nj][0],
                          half ? acc1[nj][3] : acc1[nj][1]};
            float2 q2c = {half ? acc2[nj][2] : acc2[nj][0],
                          half ? acc2[nj][3] : acc2[nj][1]};
            float* ob = out + rbase*OUTD;
            *(float2*)&ob[d_] = xv;
            *(float2*)&ob[DD + d_] = c2q;
            float2 m1 = {xv.x*c2q.x, xv.y*c2q.y};
            *(float2*)&ob[2*DD + d_] = m1;
            float2 m2 = {xv.x*q2c.x, xv.y*q2c.y};
            *(float2*)&ob[3*DD + d_] = m2;
        }
    }
}

// ---------------------------------------------------------------------------
extern "C" void kernel_launch(void* const* d_in, const int* in_sizes, int n_in,
                              void* d_out, int out_size)
{
    const float* xc   = (const float*)d_in[0];
    const float* xq   = (const float*)d_in[1];
    const float* cm   = (const float*)d_in[2];
    const float* qm   = (const float*)d_in[3];
    const float* W0   = (const float*)d_in[4];
    const float* W1   = (const float*)d_in[5];
    const float* W2   = (const float*)d_in[6];
    const float* bias = (const float*)d_in[7];
    float* out = (float*)d_out;

    k_s0<<<BB*CC/8, 256>>>(xc, W0, bias);
    k_s1<<<BB*QQ/8, 256>>>(xq, W1);
    {
        float* xcT; cudaGetSymbolAddress((void**)&xcT, g_xcT);
        float* xqT; cudaGetSymbolAddress((void**)&xqT, g_xqT);
        ktrans<<<dim3(DD/32, CC/32, BB), dim3(32,8)>>>(xc, xcT, CC, DD);
        ktrans<<<dim3(DD/32, QQ/32, BB), dim3(32,8)>>>(xq, xqT, QQ, DD);
    }
    k1_S<<<dim3(QQ/128, CC/128, BB), 256>>>(xc, xq, W2, cm, qm);
    k2c_combine<<<BB*QQ/256, 256>>>();
    k2r_combine<<<BB*CC/256, 256>>>();
    k3_A<<<dim3(QQ/64, 1, BB), 256>>>(cm);
    k4_out<<<dim3(CC/64, 1, BB), 256>>>(xc, qm, out);
}

// round 12
// speedup vs baseline: 1.4583x; 1.0934x over previous
#include <cuda_runtime.h>
#include <math.h>

#define BB 64
#define CC 1024
#define QQ 256
#define DD 128
#define OUTD (4*DD)
#define NEGV (-1e30f)
#define NCHUNK 8
#define LD 36          // f32 smem leading dim

// ---- scratch (device globals: allocation-free) ----
__device__ float g_S[(size_t)BB*CC*QQ];      // final S, 64 MB
__device__ float g_s0[BB*CC];
__device__ float g_s1[BB*QQ];
__device__ float g_pm[BB*NCHUNK*QQ];
__device__ float g_ps[BB*NCHUNK*QQ];
__device__ float g_prm[(size_t)BB*2*CC];
__device__ float g_prs[(size_t)BB*2*CC];
__device__ float g_colM[BB*QQ];
__device__ float g_colZ[BB*QQ];
__device__ float g_rowM[BB*CC];
__device__ float g_rowZ[BB*CC];
__device__ float g_AT[(size_t)BB*DD*QQ];     // (S_T @ x_cont)^T [b][d][q]
__device__ float g_xcT[(size_t)BB*DD*CC];    // xc^T [b][d][c]
__device__ float g_xqT[(size_t)BB*DD*QQ];    // xq^T [b][d][q]
__device__ float g_xcw[(size_t)BB*CC*DD];    // xc*W2 [b][c][d]

// ---------------------------------------------------------------------------
// helpers
// ---------------------------------------------------------------------------
__device__ __forceinline__ float f2tf(float x)
{
    unsigned u;
    asm("cvt.rna.tf32.f32 %0, %1;" : "=r"(u) : "f"(x));
    return __uint_as_float(u);
}

__device__ __forceinline__ void mma16808(float* c, const unsigned* a, const unsigned* b)
{
    asm volatile(
        "mma.sync.aligned.m16n8k8.row.col.f32.tf32.tf32.f32 "
        "{%0,%1,%2,%3},{%4,%5,%6,%7},{%8,%9},{%0,%1,%2,%3};"
        : "+f"(c[0]), "+f"(c[1]), "+f"(c[2]), "+f"(c[3])
        : "r"(a[0]), "r"(a[1]), "r"(a[2]), "r"(a[3]), "r"(b[0]), "r"(b[1]));
}

__device__ __forceinline__ void ldsm4f(unsigned* r, const float* p)
{
    unsigned addr = (unsigned)__cvta_generic_to_shared(p);
    asm volatile("ldmatrix.sync.aligned.m8n8.x4.shared.b16 {%0,%1,%2,%3},[%4];"
                 : "=r"(r[0]), "=r"(r[1]), "=r"(r[2]), "=r"(r[3]) : "r"(addr));
}

__device__ __forceinline__ void ldfragA(unsigned a[4], const float* tile,
                                        int row0, int ks, int lane)
{
    int m = lane >> 3;
    const float* p = tile + (row0 + ((m & 1) << 3) + (lane & 7))*LD
                          + ks + ((m >> 1) << 2);
    ldsm4f(a, p);
}

__device__ __forceinline__ void ldfragB2(unsigned bq[4], const float* tile,
                                         int nrow0, int ks, int lane)
{
    int m = lane >> 3;
    const float* p = tile + (nrow0 + ((m >> 1) << 3) + (lane & 7))*LD
                          + ks + ((m & 1) << 2);
    ldsm4f(bq, p);
}

// cp.async 16B
__device__ __forceinline__ void cp16(void* smem_dst, const void* gsrc)
{
    unsigned d = (unsigned)__cvta_generic_to_shared(smem_dst);
    asm volatile("cp.async.cg.shared.global [%0], [%1], 16;\n" :: "r"(d), "l"(gsrc));
}
__device__ __forceinline__ void cp_commit() { asm volatile("cp.async.commit_group;\n" ::); }
__device__ __forceinline__ void cp_wait1()  { asm volatile("cp.async.wait_group 1;\n" ::); }
__device__ __forceinline__ void cp_wait0()  { asm volatile("cp.async.wait_group 0;\n" ::); }

// ---------------------------------------------------------------------------
// prep: xcw = xc*W2 (direct) + xcT (transpose), one read of xc
// ---------------------------------------------------------------------------
__global__ void kprep_xc(const float* __restrict__ xc, const float* __restrict__ W2)
{
    __shared__ float t[32][33];
    int b  = blockIdx.z;
    int r0 = blockIdx.y * 32, c0 = blockIdx.x * 32;
    int x = threadIdx.x, y = threadIdx.y;
    float w = W2[c0 + x];
#pragma unroll
    for (int i = 0; i < 32; i += 8) {
        float v = xc[((size_t)b*CC + r0+y+i)*DD + c0+x];
        t[y+i][x] = v;
        g_xcw[((size_t)b*CC + r0+y+i)*DD + c0+x] = v * w;
    }
    __syncthreads();
#pragma unroll
    for (int i = 0; i < 32; i += 8)
        g_xcT[((size_t)b*DD + c0+y+i)*CC + r0+x] = t[x][y+i];
}

// transpose for xq
__global__ void ktrans(const float* __restrict__ src, float* __restrict__ dst,
                       int R, int C)
{
    __shared__ float t[32][33];
    int b  = blockIdx.z;
    int r0 = blockIdx.y * 32, c0 = blockIdx.x * 32;
    int x = threadIdx.x, y = threadIdx.y;
#pragma unroll
    for (int i = 0; i < 32; i += 8)
        t[y+i][x] = src[((size_t)b*R + r0+y+i)*C + c0+x];
    __syncthreads();
#pragma unroll
    for (int i = 0; i < 32; i += 8)
        dst[((size_t)b*C + c0+y+i)*R + r0+x] = t[x][y+i];
}

// ---------------------------------------------------------------------------
// projections
// ---------------------------------------------------------------------------
__device__ __forceinline__ float row_dot(const float* __restrict__ xr,
                                         const float* __restrict__ W, int lane)
{
    float s = 0.f;
#pragma unroll
    for (int d = 0; d < DD; d += 32) s += xr[d + lane] * W[d + lane];
#pragma unroll
    for (int o = 16; o > 0; o >>= 1) s += __shfl_xor_sync(0xffffffffu, s, o);
    return s;
}

__global__ void k_s0(const float* __restrict__ x, const float* __restrict__ W,
                     const float* __restrict__ bias)
{
    int warp = (blockIdx.x * blockDim.x + threadIdx.x) >> 5;
    int lane = threadIdx.x & 31;
    if (warp >= BB*CC) return;
    float s = row_dot(x + (size_t)warp * DD, W, lane);
    if (lane == 0) g_s0[warp] = s + bias[0];
}

__global__ void k_s1(const float* __restrict__ x, const float* __restrict__ W)
{
    int warp = (blockIdx.x * blockDim.x + threadIdx.x) >> 5;
    int lane = threadIdx.x & 31;
    if (warp >= BB*QQ) return;
    float s = row_dot(x + (size_t)warp * DD, W, lane);
    if (lane == 0) g_s1[warp] = s;
}

// ---------------------------------------------------------------------------
// K1: S = xcw @ xq^T + s0 + s1, cp.async double-buffered, + fused stats.
// BLK 128c x 128q, warp 32x64. grid (2 qblk, 8 cblk, B).
// dyn smem: As[2] 128*LD, Bs[2] 128*LD  = 73728 B
// ---------------------------------------------------------------------------
__global__ __launch_bounds__(256) void k1_S(const float* __restrict__ xcw,
                                            const float* __restrict__ xq,
                                            const float* __restrict__ cmask,
                                            const float* __restrict__ qmask)
{
    extern __shared__ float dyn[];
    float* Asb[2] = {dyn,            dyn + 128*LD};
    float* Bsb[2] = {dyn + 2*128*LD, dyn + 3*128*LD};
    __shared__ float qmn_s[128], cmn_s[128];
    __shared__ float rmaxS[128][2], rsumS[128][2];
    __shared__ float cstat[128][4], cmaxf[128];

    int b  = blockIdx.z;
    int qblk = blockIdx.x, cblk = blockIdx.y;
    int c0 = cblk * 128;
    int q0 = qblk * 128;
    int tid = threadIdx.x;
    int warp = tid >> 5, lane = tid & 31;
    int warp_m = warp >> 1, warp_n = warp & 1;
    int wm = warp_m * 32, wn = warp_n * 64;
    if (tid < 128) {
        qmn_s[tid] = NEGV * (1.f - qmask[b*QQ + q0 + tid]);
        cmn_s[tid] = NEGV * (1.f - cmask[b*CC + c0 + tid]);
    }

    auto issue = [&](int st, int k0) {
#pragma unroll
        for (int i = 0; i < 4; i++) {
            int f = tid + i*256;
            int r = f >> 3, d4 = (f & 7) * 4;
            cp16(&Asb[st][r*LD + d4], &xcw[((size_t)(b*CC + c0 + r))*DD + k0 + d4]);
            cp16(&Bsb[st][r*LD + d4], &xq [((size_t)(b*QQ + q0 + r))*DD + k0 + d4]);
        }
    };

    float acc[2][8][4] = {};
    issue(0, 0); cp_commit();

    for (int k0 = 0, st = 0; k0 < DD; k0 += 32, st ^= 1) {
        if (k0 + 32 < DD) { issue(st^1, k0+32); cp_commit(); cp_wait1(); }
        else              { cp_wait0(); }
        __syncthreads();
        const float* Ac = Asb[st];
        const float* Bc = Bsb[st];
#pragma unroll
        for (int ks = 0; ks < 32; ks += 8) {
            unsigned a0[4], a1[4];
            ldfragA(a0, Ac, wm,      ks, lane);
            ldfragA(a1, Ac, wm + 16, ks, lane);
#pragma unroll
            for (int np = 0; np < 4; np++) {
                unsigned bq[4];
                ldfragB2(bq, Bc, wn + np*16, ks, lane);
                mma16808(acc[0][np*2],   a0, bq);
                mma16808(acc[0][np*2+1], a0, bq+2);
                mma16808(acc[1][np*2],   a1, bq);
                mma16808(acc[1][np*2+1], a1, bq+2);
            }
        }
        __syncthreads();
    }

    int g = lane >> 2, tg = lane & 3;

    // ---- finalize S (add s0+s1) in-register, store ----
#pragma unroll
    for (int mi = 0; mi < 2; mi++) {
#pragma unroll
        for (int nj = 0; nj < 8; nj++) {
            int c_ = c0 + wm + mi*16 + g;
            int q_ = q0 + wn + nj*8 + tg*2;
            float s0a = g_s0[b*CC + c_];
            float s0b = g_s0[b*CC + c_ + 8];
            float s1a = g_s1[b*QQ + q_], s1b = g_s1[b*QQ + q_ + 1];
            acc[mi][nj][0] += s0a + s1a; acc[mi][nj][1] += s0a + s1b;
            acc[mi][nj][2] += s0b + s1a; acc[mi][nj][3] += s0b + s1b;
            float2 o0 = {acc[mi][nj][0], acc[mi][nj][1]};
            *(float2*)&g_S[((size_t)(b*CC + c_))*QQ + q_] = o0;
            float2 o1 = {acc[mi][nj][2], acc[mi][nj][3]};
            *(float2*)&g_S[((size_t)(b*CC + c_ + 8))*QQ + q_] = o1;
        }
    }

    // ---- row stats: partial over this block's 128-q window ----
    {
        float rmv[2][2] = {{-INFINITY,-INFINITY},{-INFINITY,-INFINITY}};
#pragma unroll
        for (int mi = 0; mi < 2; mi++)
#pragma unroll
            for (int nj = 0; nj < 8; nj++) {
                int ql = wn + nj*8 + tg*2;
                float ma = qmn_s[ql], mb = qmn_s[ql+1];
                rmv[mi][0] = fmaxf(rmv[mi][0], fmaxf(acc[mi][nj][0]+ma, acc[mi][nj][1]+mb));
                rmv[mi][1] = fmaxf(rmv[mi][1], fmaxf(acc[mi][nj][2]+ma, acc[mi][nj][3]+mb));
            }
#pragma unroll
        for (int o = 1; o <= 2; o <<= 1) {
            rmv[0][0] = fmaxf(rmv[0][0], __shfl_xor_sync(0xffffffffu, rmv[0][0], o));
            rmv[0][1] = fmaxf(rmv[0][1], __shfl_xor_sync(0xffffffffu, rmv[0][1], o));
            rmv[1][0] = fmaxf(rmv[1][0], __shfl_xor_sync(0xffffffffu, rmv[1][0], o));
            rmv[1][1] = fmaxf(rmv[1][1], __shfl_xor_sync(0xffffffffu, rmv[1][1], o));
        }
        if (tg == 0) {
#pragma unroll
            for (int mi = 0; mi < 2; mi++) {
                rmaxS[wm + mi*16 + g][warp_n]     = rmv[mi][0];
                rmaxS[wm + mi*16 + g + 8][warp_n] = rmv[mi][1];
            }
        }
        __syncthreads();
        float M00 = fmaxf(rmaxS[wm + g][0],      rmaxS[wm + g][1]);
        float M01 = fmaxf(rmaxS[wm + g + 8][0],  rmaxS[wm + g + 8][1]);
        float M10 = fmaxf(rmaxS[wm + 16 + g][0], rmaxS[wm + 16 + g][1]);
        float M11 = fmaxf(rmaxS[wm + 24 + g][0], rmaxS[wm + 24 + g][1]);
        float rs[2][2] = {};
#pragma unroll
        for (int mi = 0; mi < 2; mi++) {
            float Ma = mi ? M10 : M00, Mb = mi ? M11 : M01;
#pragma unroll
            for (int nj = 0; nj < 8; nj++) {
                int ql = wn + nj*8 + tg*2;
                float ma = qmn_s[ql], mb = qmn_s[ql+1];
                rs[mi][0] += __expf(acc[mi][nj][0]+ma - Ma) + __expf(acc[mi][nj][1]+mb - Ma);
                rs[mi][1] += __expf(acc[mi][nj][2]+ma - Mb) + __expf(acc[mi][nj][3]+mb - Mb);
            }
        }
#pragma unroll
        for (int o = 1; o <= 2; o <<= 1) {
            rs[0][0] += __shfl_xor_sync(0xffffffffu, rs[0][0], o);
            rs[0][1] += __shfl_xor_sync(0xffffffffu, rs[0][1], o);
            rs[1][0] += __shfl_xor_sync(0xffffffffu, rs[1][0], o);
            rs[1][1] += __shfl_xor_sync(0xffffffffu, rs[1][1], o);
        }
        if (tg == 0) {
#pragma unroll
            for (int mi = 0; mi < 2; mi++) {
                rsumS[wm + mi*16 + g][warp_n]     = rs[mi][0];
                rsumS[wm + mi*16 + g + 8][warp_n] = rs[mi][1];
            }
        }
        __syncthreads();
        if (tid < 128) {
            float m = fmaxf(rmaxS[tid][0], rmaxS[tid][1]);
            float s = rsumS[tid][0] + rsumS[tid][1];
            size_t idx = ((size_t)b*2 + qblk)*CC + c0 + tid;
            g_prm[idx] = m;
            g_prs[idx] = s;
        }
    }

    // ---- col stats: partial over this block's 128-c window ----
    {
        float mk0 = cmn_s[wm + g],      mk1 = cmn_s[wm + g + 8];
        float mk2 = cmn_s[wm + 16 + g], mk3 = cmn_s[wm + 24 + g];
        float cmv[8][2];
#pragma unroll
        for (int nj = 0; nj < 8; nj++) {
            cmv[nj][0] = fmaxf(fmaxf(acc[0][nj][0]+mk0, acc[0][nj][2]+mk1),
                               fmaxf(acc[1][nj][0]+mk2, acc[1][nj][2]+mk3));
            cmv[nj][1] = fmaxf(fmaxf(acc[0][nj][1]+mk0, acc[0][nj][3]+mk1),
                               fmaxf(acc[1][nj][1]+mk2, acc[1][nj][3]+mk3));
        }
#pragma unroll
        for (int o = 4; o <= 16; o <<= 1)
#pragma unroll
            for (int nj = 0; nj < 8; nj++) {
                cmv[nj][0] = fmaxf(cmv[nj][0], __shfl_xor_sync(0xffffffffu, cmv[nj][0], o));
                cmv[nj][1] = fmaxf(cmv[nj][1], __shfl_xor_sync(0xffffffffu, cmv[nj][1], o));
            }
        if (lane < 4) {
#pragma unroll
            for (int nj = 0; nj < 8; nj++) {
                int ql = wn + nj*8 + tg*2;
                cstat[ql][warp_m]   = cmv[nj][0];
                cstat[ql+1][warp_m] = cmv[nj][1];
            }
        }
        __syncthreads();
        if (tid < 128)
            cmaxf[tid] = fmaxf(fmaxf(cstat[tid][0], cstat[tid][1]),
                               fmaxf(cstat[tid][2], cstat[tid][3]));
        __syncthreads();
        float cs[8][2];
#pragma unroll
        for (int nj = 0; nj < 8; nj++) {
            int ql = wn + nj*8 + tg*2;
            float Mc0 = cmaxf[ql], Mc1 = cmaxf[ql+1];
            cs[nj][0] = __expf(acc[0][nj][0]+mk0 - Mc0) + __expf(acc[0][nj][2]+mk1 - Mc0)
                      + __expf(acc[1][nj][0]+mk2 - Mc0) + __expf(acc[1][nj][2]+mk3 - Mc0);
            cs[nj][1] = __expf(acc[0][nj][1]+mk0 - Mc1) + __expf(acc[0][nj][3]+mk1 - Mc1)
                      + __expf(acc[1][nj][1]+mk2 - Mc1) + __expf(acc[1][nj][3]+mk3 - Mc1);
        }
#pragma unroll
        for (int o = 4; o <= 16; o <<= 1)
#pragma unroll
            for (int nj = 0; nj < 8; nj++) {
                cs[nj][0] += __shfl_xor_sync(0xffffffffu, cs[nj][0], o);
                cs[nj][1] += __shfl_xor_sync(0xffffffffu, cs[nj][1], o);
            }
        __syncthreads();
        if (lane < 4) {
#pragma unroll
            for (int nj = 0; nj < 8; nj++) {
                int ql = wn + nj*8 + tg*2;
                cstat[ql][warp_m]   = cs[nj][0];
                cstat[ql+1][warp_m] = cs[nj][1];
            }
        }
        __syncthreads();
        if (tid < 128) {
            float s = cstat[tid][0] + cstat[tid][1] + cstat[tid][2] + cstat[tid][3];
            int idx = (b*NCHUNK + cblk)*QQ + q0 + tid;
            g_pm[idx] = cmaxf[tid];
            g_ps[idx] = s;
        }
    }
}

// ---------------------------------------------------------------------------
// K2c / K2r: combine partials
// ---------------------------------------------------------------------------
__global__ void k2c_combine()
{
    int idx = blockIdx.x * blockDim.x + threadIdx.x;
    if (idx >= BB*QQ) return;
    int b = idx / QQ, q = idx - b*QQ;
    float m = -INFINITY;
#pragma unroll
    for (int ch = 0; ch < NCHUNK; ch++)
        m = fmaxf(m, g_pm[(b*NCHUNK + ch)*QQ + q]);
    float s = 0.f;
#pragma unroll
    for (int ch = 0; ch < NCHUNK; ch++)
        s += g_ps[(b*NCHUNK + ch)*QQ + q] * __expf(g_pm[(b*NCHUNK + ch)*QQ + q] - m);
    g_colM[idx] = m;
    g_colZ[idx] = s;
}

__global__ void k2r_combine()
{
    int idx = blockIdx.x * blockDim.x + threadIdx.x;
    if (idx >= BB*CC) return;
    int b = idx / CC, c = idx - b*CC;
    float m0 = g_prm[((size_t)b*2 + 0)*CC + c];
    float m1 = g_prm[((size_t)b*2 + 1)*CC + c];
    float s0 = g_prs[((size_t)b*2 + 0)*CC + c];
    float s1 = g_prs[((size_t)b*2 + 1)*CC + c];
    float m = fmaxf(m0, m1);
    g_rowM[idx] = m;
    g_rowZ[idx] = s0 * __expf(m0 - m) + s1 * __expf(m1 - m);
}

// ---------------------------------------------------------------------------
// K3: AT[d][q] = sum_c xcT[d][c] * Pcol[c][q].  cp.async pipelined.
// BLK 128d x 64q, warp 32x32.
// dyn: As[2] 128*LD, Bs[2] 64*LD, Sst[2] 32*64, Cmk[2] 32  = 71936 B
// ---------------------------------------------------------------------------
__global__ __launch_bounds__(256) void k3_A(const float* __restrict__ cmask)
{
    extern __shared__ float dyn[];
    float* Asb[2] = {dyn,            dyn + 128*LD};
    float* Bsb[2] = {dyn + 2*128*LD, dyn + 2*128*LD + 64*LD};
    float* Sst[2] = {dyn + 2*128*LD + 2*64*LD, dyn + 2*128*LD + 2*64*LD + 32*64};
    float* Cmk[2] = {dyn + 2*128*LD + 2*64*LD + 2*32*64,
                     dyn + 2*128*LD + 2*64*LD + 2*32*64 + 32};
    __shared__ float cM[64], ciZ[64];

    int b  = blockIdx.z;
    int q0 = blockIdx.x * 64;
    int tid = threadIdx.x;
    int warp = tid >> 5, lane = tid & 31;
    int wm = (warp >> 1) * 32, wn = (warp & 1) * 32;
    if (tid < 64) {
        cM[tid]  = g_colM[b*QQ + q0 + tid];
        ciZ[tid] = 1.f / g_colZ[b*QQ + q0 + tid];
    }

    auto issue = [&](int st, int cc0) {
#pragma unroll
        for (int i = 0; i < 4; i++) {
            int f = tid + i*256;
            int d = f >> 3, c4 = (f & 7) * 4;
            cp16(&Asb[st][d*LD + c4], &g_xcT[((size_t)(b*DD + d))*CC + cc0 + c4]);
        }
#pragma unroll
        for (int i = 0; i < 2; i++) {
            int f = tid + i*256;
            int c = f >> 4, q4 = (f & 15) * 4;
            cp16(&Sst[st][c*64 + q4], &g_S[((size_t)(b*CC + cc0 + c))*QQ + q0 + q4]);
        }
        if (tid < 8) cp16(&Cmk[st][tid*4], &cmask[b*CC + cc0 + tid*4]);
    };

    float acc[2][4][4] = {};
    issue(0, 0); cp_commit();

    for (int cc0 = 0, st = 0; cc0 < CC; cc0 += 32, st ^= 1) {
        if (cc0 + 32 < CC) { issue(st^1, cc0+32); cp_commit(); cp_wait1(); }
        else               { cp_wait0(); }
        __syncthreads();
        // process staged S -> P^T tile (Bs)
#pragma unroll
        for (int i = 0; i < 2; i++) {
            int f = tid + i*256;
            int c = f >> 4, q4 = (f & 15) * 4;
            float4 s4 = *(float4*)&Sst[st][c*64 + q4];
            float msk = NEGV * (1.f - Cmk[st][c]);
            Bsb[st][(q4+0)*LD + c] = f2tf(__expf(s4.x + msk - cM[q4+0]) * ciZ[q4+0]);
            Bsb[st][(q4+1)*LD + c] = f2tf(__expf(s4.y + msk - cM[q4+1]) * ciZ[q4+1]);
            Bsb[st][(q4+2)*LD + c] = f2tf(__expf(s4.z + msk - cM[q4+2]) * ciZ[q4+2]);
            Bsb[st][(q4+3)*LD + c] = f2tf(__expf(s4.w + msk - cM[q4+3]) * ciZ[q4+3]);
        }
        __syncthreads();
        const float* Ac = Asb[st];
        const float* Bc = Bsb[st];
#pragma unroll
        for (int ks = 0; ks < 32; ks += 8) {
            unsigned a0[4], a1[4];
            ldfragA(a0, Ac, wm,      ks, lane);
            ldfragA(a1, Ac, wm + 16, ks, lane);
#pragma unroll
            for (int np = 0; np < 2; np++) {
                unsigned bq[4];
                ldfragB2(bq, Bc, wn + np*16, ks, lane);
                mma16808(acc[0][np*2],   a0, bq);
                mma16808(acc[0][np*2+1], a0, bq+2);
                mma16808(acc[1][np*2],   a1, bq);
                mma16808(acc[1][np*2+1], a1, bq+2);
            }
        }
        __syncthreads();
    }

    int g = lane >> 2, tg = lane & 3;
#pragma unroll
    for (int mi = 0; mi < 2; mi++) {
#pragma unroll
        for (int nj = 0; nj < 4; nj++) {
            int d_ = wm + mi*16 + g;
            int q_ = q0 + wn + nj*8 + tg*2;
            float2 o0 = {acc[mi][nj][0], acc[mi][nj][1]};
            *(float2*)&g_AT[((size_t)(b*DD + d_))*QQ + q_] = o0;
            float2 o1 = {acc[mi][nj][2], acc[mi][nj][3]};
            *(float2*)&g_AT[((size_t)(b*DD + d_ + 8))*QQ + q_] = o1;
        }
    }
}

// ---------------------------------------------------------------------------
// K4: c2q = Prow @ xq ; q2c = Prow @ A ; write concat.  cp.async pipelined.
// BLK 64c x 128d, warp 16x64.
// dyn: As[2] 64*LD, B1[2] 128*LD, B2[2] 128*LD, Sst[2] 64*32 = 108544 B
// ---------------------------------------------------------------------------
__global__ __launch_bounds__(256) void k4_out(const float* __restrict__ xc,
                                              const float* __restrict__ qmask,
                                              float* __restrict__ out)
{
    extern __shared__ float dyn[];
    float* Asb[2] = {dyn,           dyn + 64*LD};
    float* B1b[2] = {dyn + 2*64*LD,            dyn + 2*64*LD + 128*LD};
    float* B2b[2] = {dyn + 2*64*LD + 2*128*LD, dyn + 2*64*LD + 3*128*LD};
    float* Sst[2] = {dyn + 2*64*LD + 4*128*LD, dyn + 2*64*LD + 4*128*LD + 64*32};
    __shared__ float rM[64], riZ[64], qmn[QQ];

    int b  = blockIdx.z;
    int c0 = blockIdx.x * 64;
    int tid = threadIdx.x;
    int warp = tid >> 5, lane = tid & 31;
    int wm = (warp >> 1) * 16, wn = (warp & 1) * 64;
    if (tid < 64) {
        rM[tid]  = g_rowM[b*CC + c0 + tid];
        riZ[tid] = 1.f / g_rowZ[b*CC + c0 + tid];
    }
    qmn[tid] = NEGV * (1.f - qmask[b*QQ + tid]);

    auto issue = [&](int st, int qq0) {
#pragma unroll
        for (int i = 0; i < 4; i++) {
            int f = tid + i*256;
            int d = f >> 3, q4 = (f & 7) * 4;
            size_t gb = ((size_t)(b*DD + d))*QQ + qq0 + q4;
            cp16(&B1b[st][d*LD + q4], &g_xqT[gb]);
            cp16(&B2b[st][d*LD + q4], &g_AT[gb]);
        }
#pragma unroll
        for (int i = 0; i < 2; i++) {
            int f = tid + i*256;
            int c = f >> 3, q4 = (f & 7) * 4;
            cp16(&Sst[st][c*32 + q4], &g_S[((size_t)(b*CC + c0 + c))*QQ + qq0 + q4]);
        }
    };

    float acc1[8][4] = {};
    float acc2[8][4] = {};
    issue(0, 0); cp_commit();

    for (int qq0 = 0, st = 0; qq0 < QQ; qq0 += 32, st ^= 1) {
        if (qq0 + 32 < QQ) { issue(st^1, qq0+32); cp_commit(); cp_wait1(); }
        else               { cp_wait0(); }
        __syncthreads();
        // process staged S -> Prow tile (As)
#pragma unroll
        for (int i = 0; i < 2; i++) {
            int f = tid + i*256;
            int c = f >> 3, q4 = (f & 7) * 4;
            float4 s4 = *(float4*)&Sst[st][c*32 + q4];
            float m = rM[c], iz = riZ[c];
            float4 p;
            p.x = f2tf(__expf(s4.x + qmn[qq0+q4+0] - m) * iz);
            p.y = f2tf(__expf(s4.y + qmn[qq0+q4+1] - m) * iz);
            p.z = f2tf(__expf(s4.z + qmn[qq0+q4+2] - m) * iz);
            p.w = f2tf(__expf(s4.w + qmn[qq0+q4+3] - m) * iz);
            *(float4*)&Asb[st][c*LD + q4] = p;
        }
        __syncthreads();
        const float* Ac  = Asb[st];
        const float* B1c = B1b[st];
        const float* B2c = B2b[st];
#pragma unroll
        for (int ks = 0; ks < 32; ks += 8) {
            unsigned a[4];
            ldfragA(a, Ac, wm, ks, lane);
#pragma unroll
            for (int np = 0; np < 4; np++) {
                unsigned bq[4];
                ldfragB2(bq, B1c, wn + np*16, ks, lane);
                mma16808(acc1[np*2],   a, bq);
                mma16808(acc1[np*2+1], a, bq+2);
                ldfragB2(bq, B2c, wn + np*16, ks, lane);
                mma16808(acc2[np*2],   a, bq);
                mma16808(acc2[np*2+1], a, bq+2);
            }
        }
        __syncthreads();
    }

    int g = lane >> 2, tg = lane & 3;
#pragma unroll
    for (int nj = 0; nj < 8; nj++) {
        int d_ = wn + nj*8 + tg*2;
#pragma unroll
        for (int half = 0; half < 2; half++) {
            int c_ = c0 + wm + g + half*8;
            size_t rbase = (size_t)(b*CC + c_);
            float2 xv = *(const float2*)&xc[rbase*DD + d_];
            float2 c2q = {half ? acc1[nj][2] : acc1[nj][0],
                          half ? acc1[nj][3] : acc1[nj][1]};
            float2 q2c = {half ? acc2[nj][2] : acc2[nj][0],
                          half ? acc2[nj][3] : acc2[nj][1]};
            float* ob = out + rbase*OUTD;
            *(float2*)&ob[d_] = xv;
            *(float2*)&ob[DD + d_] = c2q;
            float2 m1 = {xv.x*c2q.x, xv.y*c2q.y};
            *(float2*)&ob[2*DD + d_] = m1;
            float2 m2 = {xv.x*q2c.x, xv.y*q2c.y};
            *(float2*)&ob[3*DD + d_] = m2;
        }
    }
}

// ---------------------------------------------------------------------------
extern "C" void kernel_launch(void* const* d_in, const int* in_sizes, int n_in,
                              void* d_out, int out_size)
{
    const float* xc   = (const float*)d_in[0];
    const float* xq   = (const float*)d_in[1];
    const float* cm   = (const float*)d_in[2];
    const float* qm   = (const float*)d_in[3];
    const float* W0   = (const float*)d_in[4];
    const float* W1   = (const float*)d_in[5];
    const float* W2   = (const float*)d_in[6];
    const float* bias = (const float*)d_in[7];
    float* out = (float*)d_out;

    const int SM1 = 4*128*LD*4;                                   // 73728
    const int SM3 = (2*128*LD + 2*64*LD + 2*32*64 + 2*32)*4;      // 71936
    const int SM4 = (2*64*LD + 4*128*LD + 2*64*32)*4;             // 108544
    cudaFuncSetAttribute(k1_S,  cudaFuncAttributeMaxDynamicSharedMemorySize, SM1);
    cudaFuncSetAttribute(k3_A,  cudaFuncAttributeMaxDynamicSharedMemorySize, SM3);
    cudaFuncSetAttribute(k4_out,cudaFuncAttributeMaxDynamicSharedMemorySize, SM4);

    float* xcw; cudaGetSymbolAddress((void**)&xcw, g_xcw);
    float* xqT; cudaGetSymbolAddress((void**)&xqT, g_xqT);

    k_s0<<<BB*CC/8, 256>>>(xc, W0, bias);
    k_s1<<<BB*QQ/8, 256>>>(xq, W1);
    kprep_xc<<<dim3(DD/32, CC/32, BB), dim3(32,8)>>>(xc, W2);
    ktrans<<<dim3(DD/32, QQ/32, BB), dim3(32,8)>>>(xq, xqT, QQ, DD);
    k1_S<<<dim3(QQ/128, CC/128, BB), 256, SM1>>>(xcw, xq, cm, qm);
    k2c_combine<<<BB*QQ/256, 256>>>();
    k2r_combine<<<BB*CC/256, 256>>>();
    k3_A<<<dim3(QQ/64, 1, BB), 256, SM3>>>(cm);
    k4_out<<<dim3(CC/64, 1, BB), 256, SM4>>>(xc, qm, out);
}

// round 17
// speedup vs baseline: 1.6118x; 1.1052x over previous
#include <cuda_runtime.h>
#include <math.h>

#define BB 64
#define CC 1024
#define QQ 256
#define DD 128
#define OUTD (4*DD)
#define NEGV (-1e30f)
#define LD 36          // f32 smem leading dim

// ---- scratch (device globals: allocation-free) ----
__device__ float g_E[(size_t)BB*CC*QQ];      // E = exp(S+s1+qmn), 64 MB
__device__ float g_s0[BB*CC];
__device__ float g_s1[BB*QQ];
__device__ float g_ps[BB*8*QQ];              // col partial sums (8 c-chunks)
__device__ float g_prs[(size_t)BB*2*CC];     // row partial sums (2 q-chunks)
__device__ float g_czinv[BB*QQ];             // 1/colZ'
__device__ float g_rzinv[BB*CC];             // 1/rowZ
__device__ float g_h[BB*CC];                 // exp(cmn) (0 or 1)
__device__ float g_AT[(size_t)BB*DD*QQ];     // (Pcol^T @ xc)^T [b][d][q]
__device__ float g_xcT[(size_t)BB*DD*CC];    // xc^T [b][d][c]
__device__ float g_xqT[(size_t)BB*DD*QQ];    // xq^T [b][d][q]
__device__ float g_xcw[(size_t)BB*CC*DD];    // xc*W2 [b][c][d]

// ---------------------------------------------------------------------------
// helpers
// ---------------------------------------------------------------------------
__device__ __forceinline__ float f2tf(float x)
{
    unsigned u;
    asm("cvt.rna.tf32.f32 %0, %1;" : "=r"(u) : "f"(x));
    return __uint_as_float(u);
}

__device__ __forceinline__ void mma16808(float* c, const unsigned* a, const unsigned* b)
{
    asm volatile(
        "mma.sync.aligned.m16n8k8.row.col.f32.tf32.tf32.f32 "
        "{%0,%1,%2,%3},{%4,%5,%6,%7},{%8,%9},{%0,%1,%2,%3};"
        : "+f"(c[0]), "+f"(c[1]), "+f"(c[2]), "+f"(c[3])
        : "r"(a[0]), "r"(a[1]), "r"(a[2]), "r"(a[3]), "r"(b[0]), "r"(b[1]));
}

__device__ __forceinline__ void ldsm4f(unsigned* r, const float* p)
{
    unsigned addr = (unsigned)__cvta_generic_to_shared(p);
    asm volatile("ldmatrix.sync.aligned.m8n8.x4.shared.b16 {%0,%1,%2,%3},[%4];"
                 : "=r"(r[0]), "=r"(r[1]), "=r"(r[2]), "=r"(r[3]) : "r"(addr));
}

__device__ __forceinline__ void ldfragA(unsigned a[4], const float* tile,
                                        int row0, int ks, int lane)
{
    int m = lane >> 3;
    const float* p = tile + (row0 + ((m & 1) << 3) + (lane & 7))*LD
                          + ks + ((m >> 1) << 2);
    ldsm4f(a, p);
}

__device__ __forceinline__ void ldfragB2(unsigned bq[4], const float* tile,
                                         int nrow0, int ks, int lane)
{
    int m = lane >> 3;
    const float* p = tile + (nrow0 + ((m >> 1) << 3) + (lane & 7))*LD
                          + ks + ((m & 1) << 2);
    ldsm4f(bq, p);
}

// cp.async 16B
__device__ __forceinline__ void cp16(void* smem_dst, const void* gsrc)
{
    unsigned d = (unsigned)__cvta_generic_to_shared(smem_dst);
    asm volatile("cp.async.cg.shared.global [%0], [%1], 16;\n" :: "r"(d), "l"(gsrc));
}
__device__ __forceinline__ void cp_commit() { asm volatile("cp.async.commit_group;\n" ::); }
__device__ __forceinline__ void cp_wait1()  { asm volatile("cp.async.wait_group 1;\n" ::); }
__device__ __forceinline__ void cp_wait0()  { asm volatile("cp.async.wait_group 0;\n" ::); }

// ---------------------------------------------------------------------------
// prep: xcw = xc*W2 (direct) + xcT (transpose), one read of xc
// ---------------------------------------------------------------------------
__global__ void kprep_xc(const float* __restrict__ xc, const float* __restrict__ W2)
{
    __shared__ float t[32][33];
    int b  = blockIdx.z;
    int r0 = blockIdx.y * 32, c0 = blockIdx.x * 32;
    int x = threadIdx.x, y = threadIdx.y;
    float w = W2[c0 + x];
#pragma unroll
    for (int i = 0; i < 32; i += 8) {
        float v = xc[((size_t)b*CC + r0+y+i)*DD + c0+x];
        t[y+i][x] = v;
        g_xcw[((size_t)b*CC + r0+y+i)*DD + c0+x] = v * w;
    }
    __syncthreads();
#pragma unroll
    for (int i = 0; i < 32; i += 8)
        g_xcT[((size_t)b*DD + c0+y+i)*CC + r0+x] = t[x][y+i];
}

__global__ void ktrans(const float* __restrict__ src, float* __restrict__ dst,
                       int R, int C)
{
    __shared__ float t[32][33];
    int b  = blockIdx.z;
    int r0 = blockIdx.y * 32, c0 = blockIdx.x * 32;
    int x = threadIdx.x, y = threadIdx.y;
#pragma unroll
    for (int i = 0; i < 32; i += 8)
        t[y+i][x] = src[((size_t)b*R + r0+y+i)*C + c0+x];
    __syncthreads();
#pragma unroll
    for (int i = 0; i < 32; i += 8)
        dst[((size_t)b*C + c0+y+i)*R + r0+x] = t[x][y+i];
}

// ---------------------------------------------------------------------------
// projections
// ---------------------------------------------------------------------------
__device__ __forceinline__ float row_dot(const float* __restrict__ xr,
                                         const float* __restrict__ W, int lane)
{
    float s = 0.f;
#pragma unroll
    for (int d = 0; d < DD; d += 32) s += xr[d + lane] * W[d + lane];
#pragma unroll
    for (int o = 16; o > 0; o >>= 1) s += __shfl_xor_sync(0xffffffffu, s, o);
    return s;
}

__global__ void k_s0(const float* __restrict__ x, const float* __restrict__ W,
                     const float* __restrict__ bias)
{
    int warp = (blockIdx.x * blockDim.x + threadIdx.x) >> 5;
    int lane = threadIdx.x & 31;
    if (warp >= BB*CC) return;
    float s = row_dot(x + (size_t)warp * DD, W, lane);
    if (lane == 0) g_s0[warp] = s + bias[0];
}

__global__ void k_s1(const float* __restrict__ x, const float* __restrict__ W)
{
    int warp = (blockIdx.x * blockDim.x + threadIdx.x) >> 5;
    int lane = threadIdx.x & 31;
    if (warp >= BB*QQ) return;
    float s = row_dot(x + (size_t)warp * DD, W, lane);
    if (lane == 0) g_s1[warp] = s;
}

// ---------------------------------------------------------------------------
// K1: E = exp((xcw @ xq^T) + s0 + s1 + qmn), cp.async double-buffered.
// Epilogue: partial row sums (this 128-q window) + h-weighted partial col
// sums (this 128-c window).  No max subtraction (|S| small; fp32 safe).
// BLK 128c x 128q, warp 32x64. grid (2 qblk, 8 cblk, B).
// ---------------------------------------------------------------------------
__global__ __launch_bounds__(256) void k1_S(const float* __restrict__ xcw,
                                            const float* __restrict__ xq,
                                            const float* __restrict__ cmask,
                                            const float* __restrict__ qmask)
{
    extern __shared__ float dyn[];
    float* Asb[2] = {dyn,            dyn + 128*LD};
    float* Bsb[2] = {dyn + 2*128*LD, dyn + 3*128*LD};
    __shared__ float qs_s[128];         // s1 + qmn (local q window)
    __shared__ float cmn_s[128];
    __shared__ float rsumS[128][2];
    __shared__ float cstat[128][4];

    int b  = blockIdx.z;
    int qblk = blockIdx.x, cblk = blockIdx.y;
    int c0 = cblk * 128;
    int q0 = qblk * 128;
    int tid = threadIdx.x;
    int warp = tid >> 5, lane = tid & 31;
    int warp_m = warp >> 1, warp_n = warp & 1;
    int wm = warp_m * 32, wn = warp_n * 64;
    if (tid < 128) {
        qs_s[tid]  = g_s1[b*QQ + q0 + tid] + NEGV * (1.f - qmask[b*QQ + q0 + tid]);
        cmn_s[tid] = NEGV * (1.f - cmask[b*CC + c0 + tid]);
    }

    auto issue = [&](int st, int k0) {
#pragma unroll
        for (int i = 0; i < 4; i++) {
            int f = tid + i*256;
            int r = f >> 3, d4 = (f & 7) * 4;
            cp16(&Asb[st][r*LD + d4], &xcw[((size_t)(b*CC + c0 + r))*DD + k0 + d4]);
            cp16(&Bsb[st][r*LD + d4], &xq [((size_t)(b*QQ + q0 + r))*DD + k0 + d4]);
        }
    };

    float acc[2][8][4] = {};
    issue(0, 0); cp_commit();

    for (int k0 = 0, st = 0; k0 < DD; k0 += 32, st ^= 1) {
        if (k0 + 32 < DD) { issue(st^1, k0+32); cp_commit(); cp_wait1(); }
        else              { cp_wait0(); }
        __syncthreads();
        const float* Ac = Asb[st];
        const float* Bc = Bsb[st];
#pragma unroll
        for (int ks = 0; ks < 32; ks += 8) {
            unsigned a0[4], a1[4];
            ldfragA(a0, Ac, wm,      ks, lane);
            ldfragA(a1, Ac, wm + 16, ks, lane);
#pragma unroll
            for (int np = 0; np < 4; np++) {
                unsigned bq[4];
                ldfragB2(bq, Bc, wn + np*16, ks, lane);
                mma16808(acc[0][np*2],   a0, bq);
                mma16808(acc[0][np*2+1], a0, bq+2);
                mma16808(acc[1][np*2],   a1, bq);
                mma16808(acc[1][np*2+1], a1, bq+2);
            }
        }
        __syncthreads();
    }

    int g = lane >> 2, tg = lane & 3;

    // h weights for this thread's 4 rows
    float hk0 = __expf(cmn_s[wm + g]);
    float hk1 = __expf(cmn_s[wm + g + 8]);
    float hk2 = __expf(cmn_s[wm + 16 + g]);
    float hk3 = __expf(cmn_s[wm + 24 + g]);

    float rs[2][2] = {};
    float cs[8][2] = {};

#pragma unroll
    for (int mi = 0; mi < 2; mi++) {
        int c_ = c0 + wm + mi*16 + g;
        float s0a = g_s0[b*CC + c_];
        float s0b = g_s0[b*CC + c_ + 8];
        float hA = mi ? hk2 : hk0;
        float hB = mi ? hk3 : hk1;
#pragma unroll
        for (int nj = 0; nj < 8; nj++) {
            int ql = wn + nj*8 + tg*2;
            int q_ = q0 + ql;
            float e0 = __expf(acc[mi][nj][0] + s0a + qs_s[ql]);
            float e1 = __expf(acc[mi][nj][1] + s0a + qs_s[ql+1]);
            float e2 = __expf(acc[mi][nj][2] + s0b + qs_s[ql]);
            float e3 = __expf(acc[mi][nj][3] + s0b + qs_s[ql+1]);
            float2 o0 = {e0, e1};
            *(float2*)&g_E[((size_t)(b*CC + c_))*QQ + q_] = o0;
            float2 o1 = {e2, e3};
            *(float2*)&g_E[((size_t)(b*CC + c_ + 8))*QQ + q_] = o1;
            rs[mi][0] += e0 + e1;
            rs[mi][1] += e2 + e3;
            cs[nj][0] += e0*hA + e2*hB;
            cs[nj][1] += e1*hA + e3*hB;
        }
    }

    // row partial sums: reduce over tg (q within warp), combine warp_n halves
#pragma unroll
    for (int o = 1; o <= 2; o <<= 1) {
        rs[0][0] += __shfl_xor_sync(0xffffffffu, rs[0][0], o);
        rs[0][1] += __shfl_xor_sync(0xffffffffu, rs[0][1], o);
        rs[1][0] += __shfl_xor_sync(0xffffffffu, rs[1][0], o);
        rs[1][1] += __shfl_xor_sync(0xffffffffu, rs[1][1], o);
    }
    if (tg == 0) {
#pragma unroll
        for (int mi = 0; mi < 2; mi++) {
            rsumS[wm + mi*16 + g][warp_n]     = rs[mi][0];
            rsumS[wm + mi*16 + g + 8][warp_n] = rs[mi][1];
        }
    }

    // col partial sums: reduce over g (c within warp), combine warp_m quarters
#pragma unroll
    for (int o = 4; o <= 16; o <<= 1)
#pragma unroll
        for (int nj = 0; nj < 8; nj++) {
            cs[nj][0] += __shfl_xor_sync(0xffffffffu, cs[nj][0], o);
            cs[nj][1] += __shfl_xor_sync(0xffffffffu, cs[nj][1], o);
        }
    if (lane < 4) {
#pragma unroll
        for (int nj = 0; nj < 8; nj++) {
            int ql = wn + nj*8 + tg*2;
            cstat[ql][warp_m]   = cs[nj][0];
            cstat[ql+1][warp_m] = cs[nj][1];
        }
    }
    __syncthreads();

    if (tid < 128) {
        g_prs[((size_t)b*2 + qblk)*CC + c0 + tid] = rsumS[tid][0] + rsumS[tid][1];
        g_ps[(b*8 + cblk)*QQ + q0 + tid] =
            cstat[tid][0] + cstat[tid][1] + cstat[tid][2] + cstat[tid][3];
        g_h[b*CC + c0 + tid] = __expf(cmn_s[tid]);   // idempotent across qblk
    }
}

// ---------------------------------------------------------------------------
// combines
// ---------------------------------------------------------------------------
__global__ void k2r_combine()
{
    int idx = blockIdx.x * blockDim.x + threadIdx.x;
    if (idx >= BB*CC) return;
    int b = idx / CC, c = idx - b*CC;
    float s = g_prs[((size_t)b*2 + 0)*CC + c] + g_prs[((size_t)b*2 + 1)*CC + c];
    g_rzinv[idx] = 1.f / s;
}

__global__ void k2c_combine()
{
    int idx = blockIdx.x * blockDim.x + threadIdx.x;
    if (idx >= BB*QQ) return;
    int b = idx / QQ, q = idx - b*QQ;
    float s = 0.f;
#pragma unroll
    for (int ch = 0; ch < 8; ch++) s += g_ps[(b*8 + ch)*QQ + q];
    g_czinv[idx] = 1.f / s;
}

// ---------------------------------------------------------------------------
// K3: AT[d][q] = sum_c xcT[d][c] * Pcol[c][q], Pcol = E*h*czinv (FMUL fill).
// BLK 128d x 64q, warp 32x32, cp.async pipelined.
// dyn: As[2] 128*LD, Bs[2] 64*LD, Est[2] 32*64, Hst[2] 32
// ---------------------------------------------------------------------------
__global__ __launch_bounds__(256) void k3_A()
{
    extern __shared__ float dyn[];
    float* Asb[2] = {dyn,            dyn + 128*LD};
    float* Bsb[2] = {dyn + 2*128*LD, dyn + 2*128*LD + 64*LD};
    float* Est[2] = {dyn + 2*128*LD + 2*64*LD, dyn + 2*128*LD + 2*64*LD + 32*64};
    float* Hst[2] = {dyn + 2*128*LD + 2*64*LD + 2*32*64,
                     dyn + 2*128*LD + 2*64*LD + 2*32*64 + 32};
    __shared__ float czi[64];

    int b  = blockIdx.z;
    int q0 = blockIdx.x * 64;
    int tid = threadIdx.x;
    int warp = tid >> 5, lane = tid & 31;
    int wm = (warp >> 1) * 32, wn = (warp & 1) * 32;
    if (tid < 64) czi[tid] = g_czinv[b*QQ + q0 + tid];

    auto issue = [&](int st, int cc0) {
#pragma unroll
        for (int i = 0; i < 4; i++) {
            int f = tid + i*256;
            int d = f >> 3, c4 = (f & 7) * 4;
            cp16(&Asb[st][d*LD + c4], &g_xcT[((size_t)(b*DD + d))*CC + cc0 + c4]);
        }
#pragma unroll
        for (int i = 0; i < 2; i++) {
            int f = tid + i*256;
            int c = f >> 4, q4 = (f & 15) * 4;
            cp16(&Est[st][c*64 + q4], &g_E[((size_t)(b*CC + cc0 + c))*QQ + q0 + q4]);
        }
        if (tid < 8) cp16(&Hst[st][tid*4], &g_h[b*CC + cc0 + tid*4]);
    };

    float acc[2][4][4] = {};
    issue(0, 0); cp_commit();

    for (int cc0 = 0, st = 0; cc0 < CC; cc0 += 32, st ^= 1) {
        if (cc0 + 32 < CC) { issue(st^1, cc0+32); cp_commit(); cp_wait1(); }
        else               { cp_wait0(); }
        __syncthreads();
        // Pcol^T fill: pure multiplies
#pragma unroll
        for (int i = 0; i < 2; i++) {
            int f = tid + i*256;
            int c = f >> 4, q4 = (f & 15) * 4;
            float4 e4 = *(float4*)&Est[st][c*64 + q4];
            float hc = Hst[st][c];
            Bsb[st][(q4+0)*LD + c] = f2tf(e4.x * hc * czi[q4+0]);
            Bsb[st][(q4+1)*LD + c] = f2tf(e4.y * hc * czi[q4+1]);
            Bsb[st][(q4+2)*LD + c] = f2tf(e4.z * hc * czi[q4+2]);
            Bsb[st][(q4+3)*LD + c] = f2tf(e4.w * hc * czi[q4+3]);
        }
        __syncthreads();
        const float* Ac = Asb[st];
        const float* Bc = Bsb[st];
#pragma unroll
        for (int ks = 0; ks < 32; ks += 8) {
            unsigned a0[4], a1[4];
            ldfragA(a0, Ac, wm,      ks, lane);
            ldfragA(a1, Ac, wm + 16, ks, lane);
#pragma unroll
            for (int np = 0; np < 2; np++) {
                unsigned bq[4];
                ldfragB2(bq, Bc, wn + np*16, ks, lane);
                mma16808(acc[0][np*2],   a0, bq);
                mma16808(acc[0][np*2+1], a0, bq+2);
                mma16808(acc[1][np*2],   a1, bq);
                mma16808(acc[1][np*2+1], a1, bq+2);
            }
        }
        __syncthreads();
    }

    int g = lane >> 2, tg = lane & 3;
#pragma unroll
    for (int mi = 0; mi < 2; mi++) {
#pragma unroll
        for (int nj = 0; nj < 4; nj++) {
            int d_ = wm + mi*16 + g;
            int q_ = q0 + wn + nj*8 + tg*2;
            float2 o0 = {acc[mi][nj][0], acc[mi][nj][1]};
            *(float2*)&g_AT[((size_t)(b*DD + d_))*QQ + q_] = o0;
            float2 o1 = {acc[mi][nj][2], acc[mi][nj][3]};
            *(float2*)&g_AT[((size_t)(b*DD + d_ + 8))*QQ + q_] = o1;
        }
    }
}

// ---------------------------------------------------------------------------
// K4: c2q = Prow @ xq ; q2c = Prow @ A ; write concat.  Prow = E*rzinv.
// BLK 64c x 128d, warp 16x64, cp.async pipelined.
// dyn: As[2] 64*LD, B1[2] 128*LD, B2[2] 128*LD, Est[2] 64*32
// ---------------------------------------------------------------------------
__global__ __launch_bounds__(256) void k4_out(const float* __restrict__ xc,
                                              float* __restrict__ out)
{
    extern __shared__ float dyn[];
    float* Asb[2] = {dyn,           dyn + 64*LD};
    float* B1b[2] = {dyn + 2*64*LD,            dyn + 2*64*LD + 128*LD};
    float* B2b[2] = {dyn + 2*64*LD + 2*128*LD, dyn + 2*64*LD + 3*128*LD};
    float* Est[2] = {dyn + 2*64*LD + 4*128*LD, dyn + 2*64*LD + 4*128*LD + 64*32};
    __shared__ float rzi[64];

    int b  = blockIdx.z;
    int c0 = blockIdx.x * 64;
    int tid = threadIdx.x;
    int warp = tid >> 5, lane = tid & 31;
    int wm = (warp >> 1) * 16, wn = (warp & 1) * 64;
    if (tid < 64) rzi[tid] = g_rzinv[b*CC + c0 + tid];

    auto issue = [&](int st, int qq0) {
#pragma unroll
        for (int i = 0; i < 4; i++) {
            int f = tid + i*256;
            int d = f >> 3, q4 = (f & 7) * 4;
            size_t gb = ((size_t)(b*DD + d))*QQ + qq0 + q4;
            cp16(&B1b[st][d*LD + q4], &g_xqT[gb]);
            cp16(&B2b[st][d*LD + q4], &g_AT[gb]);
        }
#pragma unroll
        for (int i = 0; i < 2; i++) {
            int f = tid + i*256;
            int c = f >> 3, q4 = (f & 7) * 4;
            cp16(&Est[st][c*32 + q4], &g_E[((size_t)(b*CC + c0 + c))*QQ + qq0 + q4]);
        }
    };

    float acc1[8][4] = {};
    float acc2[8][4] = {};
    issue(0, 0); cp_commit();

    for (int qq0 = 0, st = 0; qq0 < QQ; qq0 += 32, st ^= 1) {
        if (qq0 + 32 < QQ) { issue(st^1, qq0+32); cp_commit(); cp_wait1(); }
        else               { cp_wait0(); }
        __syncthreads();
        // Prow fill: pure multiply
#pragma unroll
        for (int i = 0; i < 2; i++) {
            int f = tid + i*256;
            int c = f >> 3, q4 = (f & 7) * 4;
            float4 e4 = *(float4*)&Est[st][c*32 + q4];
            float z = rzi[c];
            float4 p = {f2tf(e4.x*z), f2tf(e4.y*z), f2tf(e4.z*z), f2tf(e4.w*z)};
            *(float4*)&Asb[st][c*LD + q4] = p;
        }
        __syncthreads();
        const float* Ac  = Asb[st];
        const float* B1c = B1b[st];
        const float* B2c = B2b[st];
#pragma unroll
        for (int ks = 0; ks < 32; ks += 8) {
            unsigned a[4];
            ldfragA(a, Ac, wm, ks, lane);
#pragma unroll
            for (int np = 0; np < 4; np++) {
                unsigned bq[4];
                ldfragB2(bq, B1c, wn + np*16, ks, lane);
                mma16808(acc1[np*2],   a, bq);
                mma16808(acc1[np*2+1], a, bq+2);
                ldfragB2(bq, B2c, wn + np*16, ks, lane);
                mma16808(acc2[np*2],   a, bq);
                mma16808(acc2[np*2+1], a, bq+2);
            }
        }
        __syncthreads();
    }

    int g = lane >> 2, tg = lane & 3;
#pragma unroll
    for (int nj = 0; nj < 8; nj++) {
        int d_ = wn + nj*8 + tg*2;
#pragma unroll
        for (int half = 0; half < 2; half++) {
            int c_ = c0 + wm + g + half*8;
            size_t rbase = (size_t)(b*CC + c_);
            float2 xv = *(const float2*)&xc[rbase*DD + d_];
            float2 c2q = {half ? acc1[nj][2] : acc1[nj][0],
                          half ? acc1[nj][3] : acc1[nj][1]};
            float2 q2c = {half ? acc2[nj][2] : acc2[nj][0],
                          half ? acc2[nj][3] : acc2[nj][1]};
            float* ob = out + rbase*OUTD;
            *(float2*)&ob[d_] = xv;
            *(float2*)&ob[DD + d_] = c2q;
            float2 m1 = {xv.x*c2q.x, xv.y*c2q.y};
            *(float2*)&ob[2*DD + d_] = m1;
            float2 m2 = {xv.x*q2c.x, xv.y*q2c.y};
            *(float2*)&ob[3*DD + d_] = m2;
        }
    }
}

// ---------------------------------------------------------------------------
extern "C" void kernel_launch(void* const* d_in, const int* in_sizes, int n_in,
                              void* d_out, int out_size)
{
    const float* xc   = (const float*)d_in[0];
    const float* xq   = (const float*)d_in[1];
    const float* cm   = (const float*)d_in[2];
    const float* qm   = (const float*)d_in[3];
    const float* W0   = (const float*)d_in[4];
    const float* W1   = (const float*)d_in[5];
    const float* W2   = (const float*)d_in[6];
    const float* bias = (const float*)d_in[7];
    float* out = (float*)d_out;

    const int SM1 = 4*128*LD*4;                                   // 73728
    const int SM3 = (2*128*LD + 2*64*LD + 2*32*64 + 2*32)*4;      // 71936
    const int SM4 = (2*64*LD + 4*128*LD + 2*64*32)*4;             // 108544
    cudaFuncSetAttribute(k1_S,  cudaFuncAttributeMaxDynamicSharedMemorySize, SM1);
    cudaFuncSetAttribute(k3_A,  cudaFuncAttributeMaxDynamicSharedMemorySize, SM3);
    cudaFuncSetAttribute(k4_out,cudaFuncAttributeMaxDynamicSharedMemorySize, SM4);

    float* xcw; cudaGetSymbolAddress((void**)&xcw, g_xcw);
    float* xqT; cudaGetSymbolAddress((void**)&xqT, g_xqT);

    k_s0<<<BB*CC/8, 256>>>(xc, W0, bias);
    k_s1<<<BB*QQ/8, 256>>>(xq, W1);
    kprep_xc<<<dim3(DD/32, CC/32, BB), dim3(32,8)>>>(xc, W2);
    ktrans<<<dim3(DD/32, QQ/32, BB), dim3(32,8)>>>(xq, xqT, QQ, DD);
    k1_S<<<dim3(QQ/128, CC/128, BB), 256, SM1>>>(xcw, xq, cm, qm);
    k2r_combine<<<BB*CC/256, 256>>>();
    k2c_combine<<<BB*QQ/256, 256>>>();
    k3_A<<<dim3(QQ/64, 1, BB), 256, SM3>>>();
    k4_out<<<dim3(CC/64, 1, BB), 256, SM4>>>(xc, out);
}